// round 3
// baseline (speedup 1.0000x reference)
#include <cuda_runtime.h>
#include <cstdint>

#define SEQ   2048
#define EMB   1024
#define NHEAD 64
#define BATCH 8
#define ROWS  (BATCH*SEQ)   // 16384

// Scratch: Q (pre-scaled by 1/sqrt(H)), K, V. 4 MB each, static device globals
// (allocation-free per harness rules).
__device__ float g_q[(size_t)ROWS * NHEAD];
__device__ float g_k[(size_t)ROWS * NHEAD];
__device__ float g_v[(size_t)ROWS * NHEAD];

// ---------------------------------------------------------------------------
// QKV projection: [16384,1024] @ [1024,64] -> [16384,64], one weight per
// blockIdx.y. Classic tiled SGEMM: BM=64, BN=64(=NHEAD), BK=32, 256 threads,
// 4x4 register microtile per thread.
// ---------------------------------------------------------------------------
__global__ __launch_bounds__(256) void qkv_proj_kernel(
    const float* __restrict__ x,
    const float* __restrict__ Wk,
    const float* __restrict__ Wq,
    const float* __restrict__ Wv)
{
    __shared__ float As[64][33];   // x tile, padded: row stride 33 -> no LDS conflicts
    __shared__ float Bs[32][64];   // W tile, float4-friendly

    const float* W;
    float* out;
    float scale;
    if (blockIdx.y == 0)      { W = Wq; out = g_q; scale = 0.125f; } // fold 1/sqrt(64)
    else if (blockIdx.y == 1) { W = Wk; out = g_k; scale = 1.0f; }
    else                      { W = Wv; out = g_v; scale = 1.0f; }

    const int tid = threadIdx.x;
    const int tx  = tid & 15;
    const int ty  = tid >> 4;
    const int m0  = blockIdx.x * 64;

    float acc[4][4] = {};

    for (int k0 = 0; k0 < EMB; k0 += 32) {
        // Load x tile 64x32 (512 float4 / 256 threads = 2 each)
        #pragma unroll
        for (int i = 0; i < 2; i++) {
            int idx = tid + i * 256;
            int r = idx >> 3;
            int c = (idx & 7) << 2;
            float4 v = *(const float4*)(x + (size_t)(m0 + r) * EMB + k0 + c);
            As[r][c + 0] = v.x; As[r][c + 1] = v.y;
            As[r][c + 2] = v.z; As[r][c + 3] = v.w;
        }
        // Load W tile 32x64
        #pragma unroll
        for (int i = 0; i < 2; i++) {
            int idx = tid + i * 256;
            int r = idx >> 4;
            int c = (idx & 15) << 2;
            *(float4*)(&Bs[r][c]) = *(const float4*)(W + (size_t)(k0 + r) * NHEAD + c);
        }
        __syncthreads();

        #pragma unroll
        for (int k = 0; k < 32; k++) {
            float a0 = As[ty * 4 + 0][k];
            float a1 = As[ty * 4 + 1][k];
            float a2 = As[ty * 4 + 2][k];
            float a3 = As[ty * 4 + 3][k];
            float4 b = *(float4*)(&Bs[k][tx * 4]);
            acc[0][0] += a0 * b.x; acc[0][1] += a0 * b.y; acc[0][2] += a0 * b.z; acc[0][3] += a0 * b.w;
            acc[1][0] += a1 * b.x; acc[1][1] += a1 * b.y; acc[1][2] += a1 * b.z; acc[1][3] += a1 * b.w;
            acc[2][0] += a2 * b.x; acc[2][1] += a2 * b.y; acc[2][2] += a2 * b.z; acc[2][3] += a2 * b.w;
            acc[3][0] += a3 * b.x; acc[3][1] += a3 * b.y; acc[3][2] += a3 * b.z; acc[3][3] += a3 * b.w;
        }
        __syncthreads();
    }

    #pragma unroll
    for (int i = 0; i < 4; i++) {
        float4 r;
        r.x = acc[i][0] * scale;
        r.y = acc[i][1] * scale;
        r.z = acc[i][2] * scale;
        r.w = acc[i][3] * scale;
        *(float4*)(out + (size_t)(m0 + ty * 4 + i) * NHEAD + tx * 4) = r;
    }
}

// ---------------------------------------------------------------------------
// Flash-style causal attention, fp32.
// Block = 64 query rows (blockIdx.x), one batch (blockIdx.y). 256 threads.
// Warp w owns query rows [8w, 8w+8); lane owns keys/dims {lane, lane+32}.
// Smem: Qs[64][64] (broadcast reads), Ks/Vs[64][65] (padded: bank =
// (t+e)%32 distinct across lanes), Ps[64][64] (broadcast float4 reads).
// ---------------------------------------------------------------------------
#define SMEM_ATTN_FLOATS (64*64 + 64*65 + 64*65 + 64*64)
#define SMEM_ATTN_BYTES  (SMEM_ATTN_FLOATS * 4)

__global__ __launch_bounds__(256) void attn_kernel(float* __restrict__ out)
{
    extern __shared__ float sm[];
    float* Qs = sm;                  // [64][64]
    float* Ks = Qs + 64 * 64;        // [64][65]
    float* Vs = Ks + 64 * 65;        // [64][65]
    float* Ps = Vs + 64 * 65;        // [64][64]

    const int tid  = threadIdx.x;
    const int warp = tid >> 5;
    const int lane = tid & 31;
    const int qb   = blockIdx.x;     // query block, 0..31
    const int b    = blockIdx.y;     // batch, 0..7
    const size_t base = (size_t)b * SEQ * NHEAD;

    // Load Q tile (pre-scaled) once.
    const float* Qg = g_q + base + (size_t)qb * 64 * NHEAD;
    #pragma unroll
    for (int i = 0; i < 4; i++) {
        int idx = tid + i * 256;           // float4 index 0..1023
        int r = idx >> 4;
        int c = (idx & 15) << 2;
        *(float4*)(&Qs[r * 64 + c]) = *(const float4*)(Qg + (size_t)r * NHEAD + c);
    }

    float m_run[8], l_run[8], o[8][2];
    #pragma unroll
    for (int qi = 0; qi < 8; qi++) {
        m_run[qi] = -INFINITY;
        l_run[qi] = 0.0f;
        o[qi][0] = 0.0f;
        o[qi][1] = 0.0f;
    }

    const int t0 = lane;
    const int t1 = lane + 32;
    const float* qbase = Qs + warp * 8 * 64;
    float* pbase = Ps + warp * 8 * 64;

    for (int kb = 0; kb <= qb; kb++) {
        __syncthreads();   // previous iter's Ks/Vs reads done (also covers Qs on iter 0)

        const float* Kg = g_k + base + (size_t)kb * 64 * NHEAD;
        const float* Vg = g_v + base + (size_t)kb * 64 * NHEAD;
        #pragma unroll
        for (int i = 0; i < 4; i++) {
            int idx = tid + i * 256;
            int r = idx >> 4;
            int c = (idx & 15) << 2;
            float4 kv = *(const float4*)(Kg + (size_t)r * NHEAD + c);
            Ks[r * 65 + c + 0] = kv.x; Ks[r * 65 + c + 1] = kv.y;
            Ks[r * 65 + c + 2] = kv.z; Ks[r * 65 + c + 3] = kv.w;
            float4 vv = *(const float4*)(Vg + (size_t)r * NHEAD + c);
            Vs[r * 65 + c + 0] = vv.x; Vs[r * 65 + c + 1] = vv.y;
            Vs[r * 65 + c + 2] = vv.z; Vs[r * 65 + c + 3] = vv.w;
        }
        __syncthreads();

        // S = Q K^T : each thread 8 q-rows x 2 keys
        float s[8][2];
        #pragma unroll
        for (int qi = 0; qi < 8; qi++) { s[qi][0] = 0.0f; s[qi][1] = 0.0f; }

        const float* kr0 = Ks + t0 * 65;
        const float* kr1 = Ks + t1 * 65;
        #pragma unroll
        for (int e = 0; e < 64; e += 4) {
            float k00 = kr0[e + 0], k01 = kr0[e + 1], k02 = kr0[e + 2], k03 = kr0[e + 3];
            float k10 = kr1[e + 0], k11 = kr1[e + 1], k12 = kr1[e + 2], k13 = kr1[e + 3];
            #pragma unroll
            for (int qi = 0; qi < 8; qi++) {
                float4 qv = *(const float4*)(qbase + qi * 64 + e);
                s[qi][0] += qv.x * k00; s[qi][0] += qv.y * k01;
                s[qi][0] += qv.z * k02; s[qi][0] += qv.w * k03;
                s[qi][1] += qv.x * k10; s[qi][1] += qv.y * k11;
                s[qi][1] += qv.z * k12; s[qi][1] += qv.w * k13;
            }
        }

        // Causal mask on diagonal block (local indices: same 64-offset)
        if (kb == qb) {
            #pragma unroll
            for (int qi = 0; qi < 8; qi++) {
                int q = warp * 8 + qi;
                if (t0 > q) s[qi][0] = -INFINITY;
                if (t1 > q) s[qi][1] = -INFINITY;
            }
        }

        // Online softmax update
        #pragma unroll
        for (int qi = 0; qi < 8; qi++) {
            float mx = fmaxf(s[qi][0], s[qi][1]);
            #pragma unroll
            for (int off = 16; off; off >>= 1)
                mx = fmaxf(mx, __shfl_xor_sync(0xffffffffu, mx, off));
            float m_new = fmaxf(m_run[qi], mx);
            float corr = __expf(m_run[qi] - m_new);   // exp(-inf)=0 on first block
            float p0 = __expf(s[qi][0] - m_new);      // masked -> exp(-inf)=0
            float p1 = __expf(s[qi][1] - m_new);
            float ps = p0 + p1;
            #pragma unroll
            for (int off = 16; off; off >>= 1)
                ps += __shfl_xor_sync(0xffffffffu, ps, off);
            l_run[qi] = l_run[qi] * corr + ps;
            m_run[qi] = m_new;
            o[qi][0] *= corr;
            o[qi][1] *= corr;
            pbase[qi * 64 + t0] = p0;
            pbase[qi * 64 + t1] = p1;
        }
        __syncwarp();   // Ps produced/consumed within this warp only

        // O += P V : each thread 8 q-rows x 2 head-dims {lane, lane+32}
        #pragma unroll
        for (int tt = 0; tt < 64; tt += 4) {
            float v00 = Vs[(tt + 0) * 65 + lane], v01 = Vs[(tt + 0) * 65 + lane + 32];
            float v10 = Vs[(tt + 1) * 65 + lane], v11 = Vs[(tt + 1) * 65 + lane + 32];
            float v20 = Vs[(tt + 2) * 65 + lane], v21 = Vs[(tt + 2) * 65 + lane + 32];
            float v30 = Vs[(tt + 3) * 65 + lane], v31 = Vs[(tt + 3) * 65 + lane + 32];
            #pragma unroll
            for (int qi = 0; qi < 8; qi++) {
                float4 p = *(const float4*)(pbase + qi * 64 + tt);
                o[qi][0] += p.x * v00; o[qi][0] += p.y * v10;
                o[qi][0] += p.z * v20; o[qi][0] += p.w * v30;
                o[qi][1] += p.x * v01; o[qi][1] += p.y * v11;
                o[qi][1] += p.z * v21; o[qi][1] += p.w * v31;
            }
        }
    }

    // Epilogue: normalize + store
    #pragma unroll
    for (int qi = 0; qi < 8; qi++) {
        float inv = 1.0f / l_run[qi];
        size_t q = (size_t)qb * 64 + warp * 8 + qi;
        out[base + q * NHEAD + lane]      = o[qi][0] * inv;
        out[base + q * NHEAD + lane + 32] = o[qi][1] * inv;
    }
}

// ---------------------------------------------------------------------------
extern "C" void kernel_launch(void* const* d_in, const int* in_sizes, int n_in,
                              void* d_out, int out_size)
{
    (void)in_sizes; (void)n_in; (void)out_size;
    const float* x  = (const float*)d_in[0];
    const float* Wk = (const float*)d_in[1];
    const float* Wq = (const float*)d_in[2];
    const float* Wv = (const float*)d_in[3];
    float* out = (float*)d_out;

    // Idempotent, non-stream API: safe every call, including under capture.
    cudaFuncSetAttribute(attn_kernel,
                         cudaFuncAttributeMaxDynamicSharedMemorySize,
                         SMEM_ATTN_BYTES);

    qkv_proj_kernel<<<dim3(ROWS / 64, 3, 1), 256>>>(x, Wk, Wq, Wv);
    attn_kernel<<<dim3(SEQ / 64, BATCH, 1), 256, SMEM_ATTN_BYTES>>>(out);
}

// round 6
// speedup vs baseline: 1.3375x; 1.3375x over previous
#include <cuda_runtime.h>
#include <cuda_bf16.h>
#include <cstdint>

#define SEQ   2048
#define EMB   1024
#define NHEAD 64
#define BATCH 8
#define ROWS  (BATCH*SEQ)   // 16384

// Scratch: Q (pre-scaled by 1/sqrt(H)), K, V (allocation-free device globals).
__device__ float g_q[(size_t)ROWS * NHEAD];
__device__ float g_k[(size_t)ROWS * NHEAD];
__device__ float g_v[(size_t)ROWS * NHEAD];

// ---------------------------------------------------------------------------
// bf16 split helpers: v = hi + lo with |err| ~ 2^-16 |v|.
// ---------------------------------------------------------------------------
__device__ __forceinline__ void split2(float vx, float vy,
                                       uint32_t& hi, uint32_t& lo)
{
    __nv_bfloat16 hx = __float2bfloat16(vx);
    __nv_bfloat16 hy = __float2bfloat16(vy);
    __nv_bfloat16 lx = __float2bfloat16(vx - __bfloat162float(hx));
    __nv_bfloat16 ly = __float2bfloat16(vy - __bfloat162float(hy));
    hi = ((uint32_t)__bfloat16_as_ushort(hy) << 16) | __bfloat16_as_ushort(hx);
    lo = ((uint32_t)__bfloat16_as_ushort(ly) << 16) | __bfloat16_as_ushort(lx);
}

__device__ __forceinline__ void mma_bf16(float* c, const uint32_t* a,
                                         const uint32_t* b)
{
    asm volatile(
        "mma.sync.aligned.m16n8k16.row.col.f32.bf16.bf16.f32 "
        "{%0,%1,%2,%3}, {%4,%5,%6,%7}, {%8,%9}, {%0,%1,%2,%3};"
        : "+f"(c[0]), "+f"(c[1]), "+f"(c[2]), "+f"(c[3])
        : "r"(a[0]), "r"(a[1]), "r"(a[2]), "r"(a[3]), "r"(b[0]), "r"(b[1]));
}

// ---------------------------------------------------------------------------
// QKV projection via mma.sync bf16 (2-term split for ~fp32 accuracy).
// Per CTA: M=128 rows of x, N=192 (Q|K|V fused -> x read once), K=1024 in
// BK=32 chunks (2 mma k-steps of 16). 8 warps = 2 Mgroups x 4 Ngroups;
// warp tile 64x48 = 4 m-tiles x 6 n-blocks; 3 mmas per tile (hh, hl, lh).
// Smem rows padded to 36 bf16 (72B): bank = (18*row + tg) % 32 is distinct
// across all 32 lanes for every fragment load -> conflict-free.
// ---------------------------------------------------------------------------
#define AS_STRIDE 36
struct QkvSmem {
    __nv_bfloat16 Ah[128 * AS_STRIDE];
    __nv_bfloat16 Al[128 * AS_STRIDE];
    __nv_bfloat16 Bh[192 * AS_STRIDE];
    __nv_bfloat16 Bl[192 * AS_STRIDE];
};                                          // 46080 B static shared

__global__ __launch_bounds__(256) void qkv_mma_kernel(
    const float* __restrict__ x,
    const float* __restrict__ Wk,
    const float* __restrict__ Wq,
    const float* __restrict__ Wv)
{
    __shared__ QkvSmem s;
    const int tid  = threadIdx.x;
    const int warp = tid >> 5;
    const int lane = tid & 31;
    const int g    = lane >> 2;       // group id 0..7
    const int tg   = lane & 3;        // thread-in-group 0..3
    const int mg   = warp & 1;        // M group (64 rows each)
    const int ng   = warp >> 1;       // N group (48 cols each)
    const int m0   = blockIdx.x * 128;

    float c[4][6][4];
    #pragma unroll
    for (int mt = 0; mt < 4; mt++)
        #pragma unroll
        for (int nb = 0; nb < 6; nb++)
            #pragma unroll
            for (int i = 0; i < 4; i++) c[mt][nb][i] = 0.0f;

    for (int chunk = 0; chunk < 32; chunk++) {
        const int k0 = chunk * 32;
        __syncthreads();   // previous chunk's fragment reads done

        // ---- stage x tile 128x32 (1024 float4 / 256 thr = 4 each) ----
        #pragma unroll
        for (int i = 0; i < 4; i++) {
            int idx = tid + i * 256;
            int r   = idx >> 3;
            int c4  = idx & 7;
            float4 v = *(const float4*)(x + (size_t)(m0 + r) * EMB + k0 + c4 * 4);
            uint32_t h0, l0, h1, l1;
            split2(v.x, v.y, h0, l0);
            split2(v.z, v.w, h1, l1);
            uint32_t off = r * AS_STRIDE + c4 * 4;   // bf16 units, 4B-aligned
            *(uint32_t*)(s.Ah + off)     = h0;
            *(uint32_t*)(s.Ah + off + 2) = h1;
            *(uint32_t*)(s.Al + off)     = l0;
            *(uint32_t*)(s.Al + off + 2) = l1;
        }
        // ---- stage W chunks transposed: Bs[n][k], n: 0-63=Q,64-127=K,128-191=V
        #pragma unroll
        for (int i = 0; i < 6; i++) {
            int idx = tid + i * 256;          // 0..1535 float4s
            int w   = idx / 512;
            int rem = idx - w * 512;
            int kk  = rem >> 4;               // 0..31
            int n4  = (rem & 15) * 4;
            const float* Wp = (w == 0) ? Wq : ((w == 1) ? Wk : Wv);
            float4 v = *(const float4*)(Wp + (size_t)(k0 + kk) * NHEAD + n4);
            int nb0 = w * 64 + n4;
            float vv[4] = {v.x, v.y, v.z, v.w};
            #pragma unroll
            for (int j = 0; j < 4; j++) {
                __nv_bfloat16 h = __float2bfloat16(vv[j]);
                __nv_bfloat16 l = __float2bfloat16(vv[j] - __bfloat162float(h));
                s.Bh[(nb0 + j) * AS_STRIDE + kk] = h;
                s.Bl[(nb0 + j) * AS_STRIDE + kk] = l;
            }
        }
        __syncthreads();

        #pragma unroll
        for (int ks = 0; ks < 2; ks++) {
            // A fragments for 4 m-tiles (hi & lo)
            uint32_t ah[4][4], al[4][4];
            #pragma unroll
            for (int mt = 0; mt < 4; mt++) {
                int r0 = mg * 64 + mt * 16 + g;
                uint32_t o0 = r0 * AS_STRIDE + ks * 16 + 2 * tg;
                uint32_t o1 = o0 + 8 * AS_STRIDE;
                ah[mt][0] = *(const uint32_t*)(s.Ah + o0);
                ah[mt][1] = *(const uint32_t*)(s.Ah + o1);
                ah[mt][2] = *(const uint32_t*)(s.Ah + o0 + 8);
                ah[mt][3] = *(const uint32_t*)(s.Ah + o1 + 8);
                al[mt][0] = *(const uint32_t*)(s.Al + o0);
                al[mt][1] = *(const uint32_t*)(s.Al + o1);
                al[mt][2] = *(const uint32_t*)(s.Al + o0 + 8);
                al[mt][3] = *(const uint32_t*)(s.Al + o1 + 8);
            }
            #pragma unroll
            for (int nb = 0; nb < 6; nb++) {
                int n = ng * 48 + nb * 8 + g;
                uint32_t ob = n * AS_STRIDE + ks * 16 + 2 * tg;
                uint32_t bh[2], bl[2];
                bh[0] = *(const uint32_t*)(s.Bh + ob);
                bh[1] = *(const uint32_t*)(s.Bh + ob + 8);
                bl[0] = *(const uint32_t*)(s.Bl + ob);
                bl[1] = *(const uint32_t*)(s.Bl + ob + 8);
                #pragma unroll
                for (int mt = 0; mt < 4; mt++) {
                    mma_bf16(c[mt][nb], ah[mt], bh);   // hi*hi
                    mma_bf16(c[mt][nb], ah[mt], bl);   // hi*lo
                    mma_bf16(c[mt][nb], al[mt], bh);   // lo*hi
                }
            }
        }
    }

    // ---- store: n-block -> {g_q (x0.125), g_k, g_v} ----
    #pragma unroll
    for (int mt = 0; mt < 4; mt++) {
        size_t r0 = (size_t)m0 + mg * 64 + mt * 16 + g;
        #pragma unroll
        for (int nb = 0; nb < 6; nb++) {
            int n0 = ng * 48 + nb * 8;
            int w  = n0 >> 6;
            float* outp = (w == 0) ? g_q : ((w == 1) ? g_k : g_v);
            float sc    = (w == 0) ? 0.125f : 1.0f;
            int col = (n0 & 63) + 2 * tg;
            float2 v0 = make_float2(c[mt][nb][0] * sc, c[mt][nb][1] * sc);
            float2 v1 = make_float2(c[mt][nb][2] * sc, c[mt][nb][3] * sc);
            *(float2*)(outp + r0 * NHEAD + col)       = v0;
            *(float2*)(outp + (r0 + 8) * NHEAD + col) = v1;
        }
    }
}

// ---------------------------------------------------------------------------
// Flash-style causal attention, fp32. 32 query rows per CTA for occupancy
// (smem 49.7KB, grid 512). Warp w owns query rows [4w,4w+4); lane owns
// keys/dims {lane, lane+32}.
// ---------------------------------------------------------------------------
#define QTILE 32
#define SMEM_ATTN_FLOATS (QTILE*64 + 64*65 + 64*65 + QTILE*64)
#define SMEM_ATTN_BYTES  (SMEM_ATTN_FLOATS * 4)

__global__ __launch_bounds__(256) void attn_kernel(float* __restrict__ out)
{
    extern __shared__ float sm[];
    float* Qs = sm;                      // [32][64]
    float* Ks = Qs + QTILE * 64;         // [64][65]
    float* Vs = Ks + 64 * 65;            // [64][65]
    float* Ps = Vs + 64 * 65;            // [32][64]

    const int tid  = threadIdx.x;
    const int warp = tid >> 5;
    const int lane = tid & 31;
    const int qb   = blockIdx.x;         // 32-row query block
    const int b    = blockIdx.y;
    const size_t base = (size_t)b * SEQ * NHEAD;

    const float* Qg = g_q + base + (size_t)qb * QTILE * NHEAD;
    #pragma unroll
    for (int i = 0; i < 2; i++) {
        int idx = tid + i * 256;
        int r = idx >> 4;
        int c = (idx & 15) << 2;
        *(float4*)(&Qs[r * 64 + c]) = *(const float4*)(Qg + (size_t)r * NHEAD + c);
    }

    float m_run[4], l_run[4], o[4][2];
    #pragma unroll
    for (int qi = 0; qi < 4; qi++) {
        m_run[qi] = -INFINITY;
        l_run[qi] = 0.0f;
        o[qi][0] = 0.0f;
        o[qi][1] = 0.0f;
    }

    const int t0 = lane;
    const int t1 = lane + 32;
    const float* qbase = Qs + warp * 4 * 64;
    float* pbase = Ps + warp * 4 * 64;

    const int kb_last = qb >> 1;
    for (int kb = 0; kb <= kb_last; kb++) {
        __syncthreads();

        const float* Kg = g_k + base + (size_t)kb * 64 * NHEAD;
        const float* Vg = g_v + base + (size_t)kb * 64 * NHEAD;
        #pragma unroll
        for (int i = 0; i < 4; i++) {
            int idx = tid + i * 256;
            int r = idx >> 4;
            int c = (idx & 15) << 2;
            float4 kv = *(const float4*)(Kg + (size_t)r * NHEAD + c);
            Ks[r * 65 + c + 0] = kv.x; Ks[r * 65 + c + 1] = kv.y;
            Ks[r * 65 + c + 2] = kv.z; Ks[r * 65 + c + 3] = kv.w;
            float4 vv = *(const float4*)(Vg + (size_t)r * NHEAD + c);
            Vs[r * 65 + c + 0] = vv.x; Vs[r * 65 + c + 1] = vv.y;
            Vs[r * 65 + c + 2] = vv.z; Vs[r * 65 + c + 3] = vv.w;
        }
        __syncthreads();

        float sc[4][2];
        #pragma unroll
        for (int qi = 0; qi < 4; qi++) { sc[qi][0] = 0.0f; sc[qi][1] = 0.0f; }

        const float* kr0 = Ks + t0 * 65;
        const float* kr1 = Ks + t1 * 65;
        #pragma unroll
        for (int e = 0; e < 64; e += 4) {
            float k00 = kr0[e + 0], k01 = kr0[e + 1], k02 = kr0[e + 2], k03 = kr0[e + 3];
            float k10 = kr1[e + 0], k11 = kr1[e + 1], k12 = kr1[e + 2], k13 = kr1[e + 3];
            #pragma unroll
            for (int qi = 0; qi < 4; qi++) {
                float4 qv = *(const float4*)(qbase + qi * 64 + e);
                sc[qi][0] += qv.x * k00; sc[qi][0] += qv.y * k01;
                sc[qi][0] += qv.z * k02; sc[qi][0] += qv.w * k03;
                sc[qi][1] += qv.x * k10; sc[qi][1] += qv.y * k11;
                sc[qi][1] += qv.z * k12; sc[qi][1] += qv.w * k13;
            }
        }

        if (kb == kb_last) {
            #pragma unroll
            for (int qi = 0; qi < 4; qi++) {
                int qg = qb * QTILE + warp * 4 + qi;
                if (kb * 64 + t0 > qg) sc[qi][0] = -INFINITY;
                if (kb * 64 + t1 > qg) sc[qi][1] = -INFINITY;
            }
        }

        #pragma unroll
        for (int qi = 0; qi < 4; qi++) {
            float mx = fmaxf(sc[qi][0], sc[qi][1]);
            #pragma unroll
            for (int off = 16; off; off >>= 1)
                mx = fmaxf(mx, __shfl_xor_sync(0xffffffffu, mx, off));
            float m_new = fmaxf(m_run[qi], mx);
            float corr = __expf(m_run[qi] - m_new);
            float p0 = __expf(sc[qi][0] - m_new);
            float p1 = __expf(sc[qi][1] - m_new);
            float ps = p0 + p1;
            #pragma unroll
            for (int off = 16; off; off >>= 1)
                ps += __shfl_xor_sync(0xffffffffu, ps, off);
            l_run[qi] = l_run[qi] * corr + ps;
            m_run[qi] = m_new;
            o[qi][0] *= corr;
            o[qi][1] *= corr;
            pbase[qi * 64 + t0] = p0;
            pbase[qi * 64 + t1] = p1;
        }
        __syncwarp();

        #pragma unroll
        for (int tt = 0; tt < 64; tt += 4) {
            float v00 = Vs[(tt + 0) * 65 + lane], v01 = Vs[(tt + 0) * 65 + lane + 32];
            float v10 = Vs[(tt + 1) * 65 + lane], v11 = Vs[(tt + 1) * 65 + lane + 32];
            float v20 = Vs[(tt + 2) * 65 + lane], v21 = Vs[(tt + 2) * 65 + lane + 32];
            float v30 = Vs[(tt + 3) * 65 + lane], v31 = Vs[(tt + 3) * 65 + lane + 32];
            #pragma unroll
            for (int qi = 0; qi < 4; qi++) {
                float4 p = *(const float4*)(pbase + qi * 64 + tt);
                o[qi][0] += p.x * v00; o[qi][0] += p.y * v10;
                o[qi][0] += p.z * v20; o[qi][0] += p.w * v30;
                o[qi][1] += p.x * v01; o[qi][1] += p.y * v11;
                o[qi][1] += p.z * v21; o[qi][1] += p.w * v31;
            }
        }
    }

    #pragma unroll
    for (int qi = 0; qi < 4; qi++) {
        float inv = 1.0f / l_run[qi];
        size_t q = (size_t)qb * QTILE + warp * 4 + qi;
        out[base + q * NHEAD + lane]      = o[qi][0] * inv;
        out[base + q * NHEAD + lane + 32] = o[qi][1] * inv;
    }
}

// ---------------------------------------------------------------------------
extern "C" void kernel_launch(void* const* d_in, const int* in_sizes, int n_in,
                              void* d_out, int out_size)
{
    (void)in_sizes; (void)n_in; (void)out_size;
    const float* x  = (const float*)d_in[0];
    const float* Wk = (const float*)d_in[1];
    const float* Wq = (const float*)d_in[2];
    const float* Wv = (const float*)d_in[3];
    float* out = (float*)d_out;

    cudaFuncSetAttribute(attn_kernel,
                         cudaFuncAttributeMaxDynamicSharedMemorySize,
                         SMEM_ATTN_BYTES);

    qkv_mma_kernel<<<dim3(ROWS / 128, 1, 1), 256>>>(x, Wk, Wq, Wv);
    attn_kernel<<<dim3(SEQ / QTILE, BATCH, 1), 256, SMEM_ATTN_BYTES>>>(out);
}

// round 7
// speedup vs baseline: 1.8560x; 1.3876x over previous
#include <cuda_runtime.h>
#include <cuda_bf16.h>
#include <cstdint>

#define SEQ   2048
#define EMB   1024
#define NHEAD 64
#define BATCH 8
#define ROWS  (BATCH*SEQ)   // 16384

// Scratch: Q (scaled by 0.125*log2(e)), K, V (allocation-free device globals).
__device__ float g_q[(size_t)ROWS * NHEAD];
__device__ float g_k[(size_t)ROWS * NHEAD];
__device__ float g_v[(size_t)ROWS * NHEAD];

// ---------------------------------------------------------------------------
// Helpers
// ---------------------------------------------------------------------------
__device__ __forceinline__ void split2(float vx, float vy,
                                       uint32_t& hi, uint32_t& lo)
{
    __nv_bfloat16 hx = __float2bfloat16(vx);
    __nv_bfloat16 hy = __float2bfloat16(vy);
    __nv_bfloat16 lx = __float2bfloat16(vx - __bfloat162float(hx));
    __nv_bfloat16 ly = __float2bfloat16(vy - __bfloat162float(hy));
    hi = ((uint32_t)__bfloat16_as_ushort(hy) << 16) | __bfloat16_as_ushort(hx);
    lo = ((uint32_t)__bfloat16_as_ushort(ly) << 16) | __bfloat16_as_ushort(lx);
}

__device__ __forceinline__ void mma_bf16(float* c, const uint32_t* a,
                                         const uint32_t* b)
{
    asm volatile(
        "mma.sync.aligned.m16n8k16.row.col.f32.bf16.bf16.f32 "
        "{%0,%1,%2,%3}, {%4,%5,%6,%7}, {%8,%9}, {%0,%1,%2,%3};"
        : "+f"(c[0]), "+f"(c[1]), "+f"(c[2]), "+f"(c[3])
        : "r"(a[0]), "r"(a[1]), "r"(a[2]), "r"(a[3]), "r"(b[0]), "r"(b[1]));
}

__device__ __forceinline__ float ex2(float x) {
    float y;
    asm("ex2.approx.f32 %0, %1;" : "=f"(y) : "f"(x));
    return y;
}

__device__ __forceinline__ uint32_t pack_hi(float a, float b) {
    return ((uint32_t)__bfloat16_as_ushort(__float2bfloat16(b)) << 16) |
           __bfloat16_as_ushort(__float2bfloat16(a));
}
__device__ __forceinline__ uint32_t pack_lo(float a, float b) {
    float ra = a - __bfloat162float(__float2bfloat16(a));
    float rb = b - __bfloat162float(__float2bfloat16(b));
    return pack_hi(ra, rb);
}

// ---------------------------------------------------------------------------
// QKV projection via mma.sync bf16 (2-term split). Unchanged from R5 except
// the Q scale now also folds log2(e) so attention softmax runs in base 2.
// ---------------------------------------------------------------------------
#define AS_STRIDE 36
struct QkvSmem {
    __nv_bfloat16 Ah[128 * AS_STRIDE];
    __nv_bfloat16 Al[128 * AS_STRIDE];
    __nv_bfloat16 Bh[192 * AS_STRIDE];
    __nv_bfloat16 Bl[192 * AS_STRIDE];
};

#define QSCALE 0.1803368801111243f   // 0.125 * log2(e)

__global__ __launch_bounds__(256) void qkv_mma_kernel(
    const float* __restrict__ x,
    const float* __restrict__ Wk,
    const float* __restrict__ Wq,
    const float* __restrict__ Wv)
{
    __shared__ QkvSmem s;
    const int tid  = threadIdx.x;
    const int warp = tid >> 5;
    const int lane = tid & 31;
    const int g    = lane >> 2;
    const int tg   = lane & 3;
    const int mg   = warp & 1;
    const int ng   = warp >> 1;
    const int m0   = blockIdx.x * 128;

    float c[4][6][4];
    #pragma unroll
    for (int mt = 0; mt < 4; mt++)
        #pragma unroll
        for (int nb = 0; nb < 6; nb++)
            #pragma unroll
            for (int i = 0; i < 4; i++) c[mt][nb][i] = 0.0f;

    for (int chunk = 0; chunk < 32; chunk++) {
        const int k0 = chunk * 32;
        __syncthreads();

        #pragma unroll
        for (int i = 0; i < 4; i++) {
            int idx = tid + i * 256;
            int r   = idx >> 3;
            int c4  = idx & 7;
            float4 v = *(const float4*)(x + (size_t)(m0 + r) * EMB + k0 + c4 * 4);
            uint32_t h0, l0, h1, l1;
            split2(v.x, v.y, h0, l0);
            split2(v.z, v.w, h1, l1);
            uint32_t off = r * AS_STRIDE + c4 * 4;
            *(uint32_t*)(s.Ah + off)     = h0;
            *(uint32_t*)(s.Ah + off + 2) = h1;
            *(uint32_t*)(s.Al + off)     = l0;
            *(uint32_t*)(s.Al + off + 2) = l1;
        }
        #pragma unroll
        for (int i = 0; i < 6; i++) {
            int idx = tid + i * 256;
            int w   = idx / 512;
            int rem = idx - w * 512;
            int kk  = rem >> 4;
            int n4  = (rem & 15) * 4;
            const float* Wp = (w == 0) ? Wq : ((w == 1) ? Wk : Wv);
            float4 v = *(const float4*)(Wp + (size_t)(k0 + kk) * NHEAD + n4);
            int nb0 = w * 64 + n4;
            float vv[4] = {v.x, v.y, v.z, v.w};
            #pragma unroll
            for (int j = 0; j < 4; j++) {
                __nv_bfloat16 h = __float2bfloat16(vv[j]);
                __nv_bfloat16 l = __float2bfloat16(vv[j] - __bfloat162float(h));
                s.Bh[(nb0 + j) * AS_STRIDE + kk] = h;
                s.Bl[(nb0 + j) * AS_STRIDE + kk] = l;
            }
        }
        __syncthreads();

        #pragma unroll
        for (int ks = 0; ks < 2; ks++) {
            uint32_t ah[4][4], al[4][4];
            #pragma unroll
            for (int mt = 0; mt < 4; mt++) {
                int r0 = mg * 64 + mt * 16 + g;
                uint32_t o0 = r0 * AS_STRIDE + ks * 16 + 2 * tg;
                uint32_t o1 = o0 + 8 * AS_STRIDE;
                ah[mt][0] = *(const uint32_t*)(s.Ah + o0);
                ah[mt][1] = *(const uint32_t*)(s.Ah + o1);
                ah[mt][2] = *(const uint32_t*)(s.Ah + o0 + 8);
                ah[mt][3] = *(const uint32_t*)(s.Ah + o1 + 8);
                al[mt][0] = *(const uint32_t*)(s.Al + o0);
                al[mt][1] = *(const uint32_t*)(s.Al + o1);
                al[mt][2] = *(const uint32_t*)(s.Al + o0 + 8);
                al[mt][3] = *(const uint32_t*)(s.Al + o1 + 8);
            }
            #pragma unroll
            for (int nb = 0; nb < 6; nb++) {
                int n = ng * 48 + nb * 8 + g;
                uint32_t ob = n * AS_STRIDE + ks * 16 + 2 * tg;
                uint32_t bh[2], bl[2];
                bh[0] = *(const uint32_t*)(s.Bh + ob);
                bh[1] = *(const uint32_t*)(s.Bh + ob + 8);
                bl[0] = *(const uint32_t*)(s.Bl + ob);
                bl[1] = *(const uint32_t*)(s.Bl + ob + 8);
                #pragma unroll
                for (int mt = 0; mt < 4; mt++) {
                    mma_bf16(c[mt][nb], ah[mt], bh);
                    mma_bf16(c[mt][nb], ah[mt], bl);
                    mma_bf16(c[mt][nb], al[mt], bh);
                }
            }
        }
    }

    #pragma unroll
    for (int mt = 0; mt < 4; mt++) {
        size_t r0 = (size_t)m0 + mg * 64 + mt * 16 + g;
        #pragma unroll
        for (int nb = 0; nb < 6; nb++) {
            int n0 = ng * 48 + nb * 8;
            int w  = n0 >> 6;
            float* outp = (w == 0) ? g_q : ((w == 1) ? g_k : g_v);
            float sc    = (w == 0) ? QSCALE : 1.0f;
            int col = (n0 & 63) + 2 * tg;
            float2 v0 = make_float2(c[mt][nb][0] * sc, c[mt][nb][1] * sc);
            float2 v1 = make_float2(c[mt][nb][2] * sc, c[mt][nb][3] * sc);
            *(float2*)(outp + r0 * NHEAD + col)       = v0;
            *(float2*)(outp + (r0 + 8) * NHEAD + col) = v1;
        }
    }
}

// ---------------------------------------------------------------------------
// Tensor-core flash attention (mma.sync bf16 3-term split, base-2 softmax).
// CTA: 64 queries, 4 warps (16 rows each), loop over 64-key blocks.
// S accumulator fragments are reused directly as P A-fragments for the PV
// mma (layout identity) -> no smem round-trip for P.
// Smem (dynamic, 55296 B): Qh/Ql, Kh/Kl [row][head] and Vh/Vl transposed
// [head][key], all stride 72 bf16 (36 u32) -> conflict-free fragment LDS.
// ---------------------------------------------------------------------------
#define STR   72
#define STR32 36
#define TILE_E (64 * STR)              // bf16 elems per tile
#define ATTN_SMEM_BYTES (6 * TILE_E * 2)

__global__ __launch_bounds__(128) void attn_mma_kernel(float* __restrict__ out)
{
    extern __shared__ __nv_bfloat16 sm[];
    __nv_bfloat16* Qh = sm;
    __nv_bfloat16* Ql = Qh + TILE_E;
    __nv_bfloat16* Kh = Ql + TILE_E;
    __nv_bfloat16* Kl = Kh + TILE_E;
    __nv_bfloat16* Vh = Kl + TILE_E;   // transposed: [d][t]
    __nv_bfloat16* Vl = Vh + TILE_E;

    const uint32_t* Qh32 = (const uint32_t*)Qh;
    const uint32_t* Ql32 = (const uint32_t*)Ql;
    const uint32_t* Kh32 = (const uint32_t*)Kh;
    const uint32_t* Kl32 = (const uint32_t*)Kl;
    const uint32_t* Vh32 = (const uint32_t*)Vh;
    const uint32_t* Vl32 = (const uint32_t*)Vl;

    const int tid  = threadIdx.x;
    const int warp = tid >> 5;
    const int lane = tid & 31;
    const int g    = lane >> 2;
    const int tg   = lane & 3;
    const int qb   = blockIdx.x;               // 64-row query tile, 0..31
    const int b    = blockIdx.y;
    const size_t base = (size_t)b * SEQ * NHEAD;
    const int q0   = qb * 64;

    // ---- stage Q once: 64x64 f32 -> split bf16, stride 72 ----
    {
        const float* Qg = g_q + base + (size_t)q0 * NHEAD;
        #pragma unroll
        for (int i = 0; i < 8; i++) {
            int idx = tid + i * 128;
            int r   = idx >> 4;
            int c4  = (idx & 15) * 4;
            float4 v = *(const float4*)(Qg + (size_t)r * NHEAD + c4);
            uint32_t h0, l0, h1, l1;
            split2(v.x, v.y, h0, l0);
            split2(v.z, v.w, h1, l1);
            uint32_t off = r * STR + c4;
            *(uint32_t*)(Qh + off)     = h0;
            *(uint32_t*)(Qh + off + 2) = h1;
            *(uint32_t*)(Ql + off)     = l0;
            *(uint32_t*)(Ql + off + 2) = l1;
        }
    }

    float o[8][4];
    #pragma unroll
    for (int nb = 0; nb < 8; nb++)
        #pragma unroll
        for (int i = 0; i < 4; i++) o[nb][i] = 0.0f;
    float mrun[2] = {-1e30f, -1e30f};
    float lrun[2] = {0.0f, 0.0f};

    for (int kb = 0; kb <= qb; kb++) {
        __syncthreads();   // prior iter's K/V fragment reads done (covers Q iter0)

        // ---- stage K (rows=keys) and V transposed (rows=dims) ----
        const float* Kg = g_k + base + (size_t)kb * 64 * NHEAD;
        const float* Vg = g_v + base + (size_t)kb * 64 * NHEAD;
        #pragma unroll
        for (int i = 0; i < 8; i++) {
            int idx = tid + i * 128;
            int r   = idx >> 4;        // key index
            int c4  = (idx & 15) * 4;  // head-dim start
            float4 kv = *(const float4*)(Kg + (size_t)r * NHEAD + c4);
            uint32_t h0, l0, h1, l1;
            split2(kv.x, kv.y, h0, l0);
            split2(kv.z, kv.w, h1, l1);
            uint32_t off = r * STR + c4;
            *(uint32_t*)(Kh + off)     = h0;
            *(uint32_t*)(Kh + off + 2) = h1;
            *(uint32_t*)(Kl + off)     = l0;
            *(uint32_t*)(Kl + off + 2) = l1;

            float4 vv = *(const float4*)(Vg + (size_t)r * NHEAD + c4);
            float va[4] = {vv.x, vv.y, vv.z, vv.w};
            #pragma unroll
            for (int j = 0; j < 4; j++) {
                __nv_bfloat16 h = __float2bfloat16(va[j]);
                __nv_bfloat16 l = __float2bfloat16(va[j] - __bfloat162float(h));
                Vh[(c4 + j) * STR + r] = h;   // transposed [d][t]
                Vl[(c4 + j) * STR + r] = l;
            }
        }
        __syncthreads();

        // ---- S = Q K^T (fragments; 3-term split) ----
        float s[8][4];
        #pragma unroll
        for (int nb = 0; nb < 8; nb++)
            #pragma unroll
            for (int i = 0; i < 4; i++) s[nb][i] = 0.0f;

        #pragma unroll
        for (int ks = 0; ks < 4; ks++) {
            uint32_t qh[4], ql[4];
            uint32_t o0 = (warp * 16 + g) * STR32 + ks * 8 + tg;
            uint32_t o1 = o0 + 8 * STR32;
            qh[0] = Qh32[o0]; qh[1] = Qh32[o1];
            qh[2] = Qh32[o0 + 4]; qh[3] = Qh32[o1 + 4];
            ql[0] = Ql32[o0]; ql[1] = Ql32[o1];
            ql[2] = Ql32[o0 + 4]; ql[3] = Ql32[o1 + 4];
            #pragma unroll
            for (int nb = 0; nb < 8; nb++) {
                uint32_t ob = (nb * 8 + g) * STR32 + ks * 8 + tg;
                uint32_t bh[2], bl[2];
                bh[0] = Kh32[ob]; bh[1] = Kh32[ob + 4];
                bl[0] = Kl32[ob]; bl[1] = Kl32[ob + 4];
                mma_bf16(s[nb], qh, bh);
                mma_bf16(s[nb], qh, bl);
                mma_bf16(s[nb], ql, bh);
            }
        }

        // ---- causal mask (only the diagonal block) ----
        if (kb == qb) {
            int r0 = q0 + warp * 16 + g;
            #pragma unroll
            for (int nb = 0; nb < 8; nb++) {
                int col = kb * 64 + nb * 8 + 2 * tg;
                if (col     > r0)     s[nb][0] = -1e30f;
                if (col + 1 > r0)     s[nb][1] = -1e30f;
                if (col     > r0 + 8) s[nb][2] = -1e30f;
                if (col + 1 > r0 + 8) s[nb][3] = -1e30f;
            }
        }

        // ---- online softmax (base-2; quad reductions) ----
        float mx0 = -1e30f, mx1 = -1e30f;
        #pragma unroll
        for (int nb = 0; nb < 8; nb++) {
            mx0 = fmaxf(mx0, fmaxf(s[nb][0], s[nb][1]));
            mx1 = fmaxf(mx1, fmaxf(s[nb][2], s[nb][3]));
        }
        mx0 = fmaxf(mx0, __shfl_xor_sync(0xffffffffu, mx0, 1));
        mx0 = fmaxf(mx0, __shfl_xor_sync(0xffffffffu, mx0, 2));
        mx1 = fmaxf(mx1, __shfl_xor_sync(0xffffffffu, mx1, 1));
        mx1 = fmaxf(mx1, __shfl_xor_sync(0xffffffffu, mx1, 2));

        float mn0 = fmaxf(mrun[0], mx0);
        float mn1 = fmaxf(mrun[1], mx1);
        float corr0 = ex2(mrun[0] - mn0);
        float corr1 = ex2(mrun[1] - mn1);
        mrun[0] = mn0; mrun[1] = mn1;

        float ps0 = 0.0f, ps1 = 0.0f;
        #pragma unroll
        for (int nb = 0; nb < 8; nb++) {
            s[nb][0] = ex2(s[nb][0] - mn0);
            s[nb][1] = ex2(s[nb][1] - mn0);
            s[nb][2] = ex2(s[nb][2] - mn1);
            s[nb][3] = ex2(s[nb][3] - mn1);
            ps0 += s[nb][0] + s[nb][1];
            ps1 += s[nb][2] + s[nb][3];
        }
        ps0 += __shfl_xor_sync(0xffffffffu, ps0, 1);
        ps0 += __shfl_xor_sync(0xffffffffu, ps0, 2);
        ps1 += __shfl_xor_sync(0xffffffffu, ps1, 1);
        ps1 += __shfl_xor_sync(0xffffffffu, ps1, 2);
        lrun[0] = lrun[0] * corr0 + ps0;
        lrun[1] = lrun[1] * corr1 + ps1;

        #pragma unroll
        for (int nb = 0; nb < 8; nb++) {
            o[nb][0] *= corr0; o[nb][1] *= corr0;
            o[nb][2] *= corr1; o[nb][3] *= corr1;
        }

        // ---- O += P V (P from S fragments in-register; 3-term split) ----
        #pragma unroll
        for (int ks = 0; ks < 4; ks++) {
            uint32_t ph[4], pl[4];
            ph[0] = pack_hi(s[2*ks][0],   s[2*ks][1]);
            ph[1] = pack_hi(s[2*ks][2],   s[2*ks][3]);
            ph[2] = pack_hi(s[2*ks+1][0], s[2*ks+1][1]);
            ph[3] = pack_hi(s[2*ks+1][2], s[2*ks+1][3]);
            pl[0] = pack_lo(s[2*ks][0],   s[2*ks][1]);
            pl[1] = pack_lo(s[2*ks][2],   s[2*ks][3]);
            pl[2] = pack_lo(s[2*ks+1][0], s[2*ks+1][1]);
            pl[3] = pack_lo(s[2*ks+1][2], s[2*ks+1][3]);
            #pragma unroll
            for (int nb = 0; nb < 8; nb++) {
                uint32_t ob = (nb * 8 + g) * STR32 + ks * 8 + tg;
                uint32_t vh[2], vl[2];
                vh[0] = Vh32[ob]; vh[1] = Vh32[ob + 4];
                vl[0] = Vl32[ob]; vl[1] = Vl32[ob + 4];
                mma_bf16(o[nb], ph, vh);
                mma_bf16(o[nb], ph, vl);
                mma_bf16(o[nb], pl, vh);
            }
        }
    }

    // ---- epilogue ----
    float inv0 = 1.0f / lrun[0];
    float inv1 = 1.0f / lrun[1];
    size_t r0 = (size_t)q0 + warp * 16 + g;
    #pragma unroll
    for (int nb = 0; nb < 8; nb++) {
        int col = nb * 8 + 2 * tg;
        *(float2*)(out + base + r0 * NHEAD + col) =
            make_float2(o[nb][0] * inv0, o[nb][1] * inv0);
        *(float2*)(out + base + (r0 + 8) * NHEAD + col) =
            make_float2(o[nb][2] * inv1, o[nb][3] * inv1);
    }
}

// ---------------------------------------------------------------------------
extern "C" void kernel_launch(void* const* d_in, const int* in_sizes, int n_in,
                              void* d_out, int out_size)
{
    (void)in_sizes; (void)n_in; (void)out_size;
    const float* x  = (const float*)d_in[0];
    const float* Wk = (const float*)d_in[1];
    const float* Wq = (const float*)d_in[2];
    const float* Wv = (const float*)d_in[3];
    float* out = (float*)d_out;

    cudaFuncSetAttribute(attn_mma_kernel,
                         cudaFuncAttributeMaxDynamicSharedMemorySize,
                         ATTN_SMEM_BYTES);

    qkv_mma_kernel<<<dim3(ROWS / 128, 1, 1), 256>>>(x, Wk, Wq, Wv);
    attn_mma_kernel<<<dim3(SEQ / 64, BATCH, 1), 128, ATTN_SMEM_BYTES>>>(out);
}

// round 9
// speedup vs baseline: 2.1307x; 1.1480x over previous
#include <cuda_runtime.h>
#include <cuda_bf16.h>
#include <cstdint>

#define SEQ   2048
#define EMB   1024
#define NHEAD 64
#define BATCH 8
#define ROWS  (BATCH*SEQ)   // 16384

// Split-bf16 scratch produced by qkv kernel (allocation-free device globals).
// q/k: [row][64] as u32 pairs (32 u32/row). v: transposed per 64-row block:
// [(b*32+kb)*64 + d][t] bf16. 16B-aligned: cp.async.16 requires it.
__device__ __align__(16) uint32_t      g_qh[(size_t)ROWS * 32], g_ql[(size_t)ROWS * 32];
__device__ __align__(16) uint32_t      g_kh[(size_t)ROWS * 32], g_kl[(size_t)ROWS * 32];
__device__ __align__(16) __nv_bfloat16 g_vth[(size_t)ROWS * 64], g_vtl[(size_t)ROWS * 64];

#define QSCALE 0.1803368801111243f   // 0.125 * log2(e): base-2 softmax

// ---------------------------------------------------------------------------
// Helpers
// ---------------------------------------------------------------------------
__device__ __forceinline__ void split2(float vx, float vy,
                                       uint32_t& hi, uint32_t& lo)
{
    __nv_bfloat16 hx = __float2bfloat16(vx);
    __nv_bfloat16 hy = __float2bfloat16(vy);
    __nv_bfloat16 lx = __float2bfloat16(vx - __bfloat162float(hx));
    __nv_bfloat16 ly = __float2bfloat16(vy - __bfloat162float(hy));
    hi = ((uint32_t)__bfloat16_as_ushort(hy) << 16) | __bfloat16_as_ushort(hx);
    lo = ((uint32_t)__bfloat16_as_ushort(ly) << 16) | __bfloat16_as_ushort(lx);
}

__device__ __forceinline__ void mma_bf16(float* c, const uint32_t* a,
                                         const uint32_t* b)
{
    asm volatile(
        "mma.sync.aligned.m16n8k16.row.col.f32.bf16.bf16.f32 "
        "{%0,%1,%2,%3}, {%4,%5,%6,%7}, {%8,%9}, {%0,%1,%2,%3};"
        : "+f"(c[0]), "+f"(c[1]), "+f"(c[2]), "+f"(c[3])
        : "r"(a[0]), "r"(a[1]), "r"(a[2]), "r"(a[3]), "r"(b[0]), "r"(b[1]));
}

__device__ __forceinline__ float ex2(float x) {
    float y;
    asm("ex2.approx.f32 %0, %1;" : "=f"(y) : "f"(x));
    return y;
}

__device__ __forceinline__ uint32_t pack_hi(float a, float b) {
    return ((uint32_t)__bfloat16_as_ushort(__float2bfloat16(b)) << 16) |
           __bfloat16_as_ushort(__float2bfloat16(a));
}
__device__ __forceinline__ uint32_t pack_lo(float a, float b) {
    float ra = a - __bfloat162float(__float2bfloat16(a));
    float rb = b - __bfloat162float(__float2bfloat16(b));
    return pack_hi(ra, rb);
}

__device__ __forceinline__ uint32_t smem_u32p(const void* p) {
    uint32_t a;
    asm("{ .reg .u64 t; cvta.to.shared.u64 t, %1; cvt.u32.u64 %0, t; }"
        : "=r"(a) : "l"(p));
    return a;
}
__device__ __forceinline__ void cp16(uint32_t dst, const void* src) {
    asm volatile("cp.async.ca.shared.global [%0], [%1], 16;"
                 :: "r"(dst), "l"(src));
}
#define CP_COMMIT()  asm volatile("cp.async.commit_group;" ::: "memory")
#define CP_WAIT(n)   asm volatile("cp.async.wait_group %0;" :: "n"(n) : "memory")

// ---------------------------------------------------------------------------
// QKV projection via mma.sync bf16 (2-term split, ~fp32 accuracy).
// M=64/CTA (grid 256 fills all SMs, 2 CTAs/SM), N=192 (Q|K|V fused), K in
// 32-wide chunks. Register-prefetch double buffer: next chunk's LDGs are in
// flight during the current chunk's MMAs.
// Epilogue writes split-bf16 q/k (row-major u32 pairs) and v (transposed
// per 64-block) so the attention kernel never converts.
// ---------------------------------------------------------------------------
__global__ __launch_bounds__(256, 2) void qkv_mma_kernel(
    const float* __restrict__ x,
    const float* __restrict__ Wk,
    const float* __restrict__ Wq,
    const float* __restrict__ Wv)
{
    __shared__ __nv_bfloat16 Ah[64 * 36], Al[64 * 36];
    __shared__ __nv_bfloat16 Bh[192 * 36], Bl[192 * 36];

    const int tid  = threadIdx.x;
    const int warp = tid >> 5;
    const int lane = tid & 31;
    const int g    = lane >> 2;
    const int tg   = lane & 3;
    const int mg   = warp & 1;        // 32-row half
    const int ng   = warp >> 1;       // 48-col group
    const int m0   = blockIdx.x * 64;

    float acc[2][6][4];
    #pragma unroll
    for (int mt = 0; mt < 2; mt++)
        #pragma unroll
        for (int nb = 0; nb < 6; nb++)
            #pragma unroll
            for (int i = 0; i < 4; i++) acc[mt][nb][i] = 0.0f;

    // prefetch registers
    float4 xa[2], wa[6];
    const int xr  = tid >> 3;
    const int xc4 = (tid & 7) * 4;
    int wkk[6], wn4[6];
    #pragma unroll
    for (int i = 0; i < 6; i++) {
        int idx = tid + i * 256;
        int w   = idx / 512;
        int rem = idx - w * 512;
        wkk[i] = rem >> 4;
        wn4[i] = (rem & 15) * 4;
    }

    #define LOAD_G(chunk) do {                                                 \
        int k0_ = (chunk) * 32;                                                \
        xa[0] = *(const float4*)(x + (size_t)(m0 + xr) * EMB + k0_ + xc4);     \
        xa[1] = *(const float4*)(x + (size_t)(m0 + xr + 32) * EMB + k0_ + xc4);\
        _Pragma("unroll")                                                      \
        for (int i_ = 0; i_ < 6; i_++) {                                       \
            int w_ = (tid + i_ * 256) / 512;                                   \
            const float* Wp_ = (w_ == 0) ? Wq : ((w_ == 1) ? Wk : Wv);         \
            wa[i_] = *(const float4*)(Wp_ + (size_t)(k0_ + wkk[i_]) * NHEAD + wn4[i_]); \
        }                                                                      \
    } while (0)

    LOAD_G(0);

    for (int chunk = 0; chunk < 32; chunk++) {
        __syncthreads();   // consumers of previous chunk's smem done

        // ---- store staged regs -> smem (with split) ----
        #pragma unroll
        for (int i = 0; i < 2; i++) {
            int r = xr + i * 32;
            uint32_t h0, l0, h1, l1;
            split2(xa[i].x, xa[i].y, h0, l0);
            split2(xa[i].z, xa[i].w, h1, l1);
            uint32_t off = r * 36 + xc4;
            *(uint32_t*)(Ah + off)     = h0;
            *(uint32_t*)(Ah + off + 2) = h1;
            *(uint32_t*)(Al + off)     = l0;
            *(uint32_t*)(Al + off + 2) = l1;
        }
        #pragma unroll
        for (int i = 0; i < 6; i++) {
            int w   = (tid + i * 256) / 512;
            int nb0 = w * 64 + wn4[i];
            float vv[4] = {wa[i].x, wa[i].y, wa[i].z, wa[i].w};
            #pragma unroll
            for (int j = 0; j < 4; j++) {
                __nv_bfloat16 h = __float2bfloat16(vv[j]);
                __nv_bfloat16 l = __float2bfloat16(vv[j] - __bfloat162float(h));
                Bh[(nb0 + j) * 36 + wkk[i]] = h;
                Bl[(nb0 + j) * 36 + wkk[i]] = l;
            }
        }
        __syncthreads();

        if (chunk < 31) LOAD_G(chunk + 1);   // overlap with MMA below

        #pragma unroll
        for (int ks = 0; ks < 2; ks++) {
            uint32_t ah[2][4], al2[2][4];
            #pragma unroll
            for (int mt = 0; mt < 2; mt++) {
                int r0 = mg * 32 + mt * 16 + g;
                uint32_t o0 = r0 * 36 + ks * 16 + 2 * tg;   // bf16 index
                uint32_t o1 = o0 + 8 * 36;
                ah[mt][0] = *(const uint32_t*)(Ah + o0);
                ah[mt][1] = *(const uint32_t*)(Ah + o1);
                ah[mt][2] = *(const uint32_t*)(Ah + o0 + 8);
                ah[mt][3] = *(const uint32_t*)(Ah + o1 + 8);
                al2[mt][0] = *(const uint32_t*)(Al + o0);
                al2[mt][1] = *(const uint32_t*)(Al + o1);
                al2[mt][2] = *(const uint32_t*)(Al + o0 + 8);
                al2[mt][3] = *(const uint32_t*)(Al + o1 + 8);
            }
            #pragma unroll
            for (int nb = 0; nb < 6; nb++) {
                int n = ng * 48 + nb * 8 + g;
                uint32_t ob = n * 36 + ks * 16 + 2 * tg;
                uint32_t bh[2], bl[2];
                bh[0] = *(const uint32_t*)(Bh + ob);
                bh[1] = *(const uint32_t*)(Bh + ob + 8);
                bl[0] = *(const uint32_t*)(Bl + ob);
                bl[1] = *(const uint32_t*)(Bl + ob + 8);
                #pragma unroll
                for (int mt = 0; mt < 2; mt++) {
                    mma_bf16(acc[mt][nb], ah[mt], bh);
                    mma_bf16(acc[mt][nb], ah[mt], bl);
                    mma_bf16(acc[mt][nb], al2[mt], bh);
                }
            }
        }
    }

    // ---- epilogue: write split-bf16 q/k (row-major) and v (transposed) ----
    const int b_  = m0 >> 11;          // batch
    const int kb_ = (m0 >> 6) & 31;    // 64-block within seq (CTA-uniform)
    const size_t vrow0 = ((size_t)(b_ * 32 + kb_)) * 64;

    #pragma unroll
    for (int mt = 0; mt < 2; mt++) {
        size_t r0 = (size_t)m0 + mg * 32 + mt * 16 + g;
        int    t0 = (int)(r0 & 63);
        #pragma unroll
        for (int nb = 0; nb < 6; nb++) {
            int n0  = ng * 48 + nb * 8;
            int w   = n0 >> 6;
            int col = (n0 & 63) + 2 * tg;
            float v00 = acc[mt][nb][0], v01 = acc[mt][nb][1];
            float v10 = acc[mt][nb][2], v11 = acc[mt][nb][3];
            if (w == 0) {
                v00 *= QSCALE; v01 *= QSCALE; v10 *= QSCALE; v11 *= QSCALE;
                size_t i0 = r0 * 32 + (col >> 1);
                g_qh[i0]       = pack_hi(v00, v01);
                g_ql[i0]       = pack_lo(v00, v01);
                g_qh[i0 + 256] = pack_hi(v10, v11);   // (r0+8)*32
                g_ql[i0 + 256] = pack_lo(v10, v11);
            } else if (w == 1) {
                size_t i0 = r0 * 32 + (col >> 1);
                g_kh[i0]       = pack_hi(v00, v01);
                g_kl[i0]       = pack_lo(v00, v01);
                g_kh[i0 + 256] = pack_hi(v10, v11);
                g_kl[i0 + 256] = pack_lo(v10, v11);
            } else {
                // transposed: [vrow0 + d][t]
                size_t iA = (vrow0 + col) * 64 + t0;
                size_t iB = (vrow0 + col + 1) * 64 + t0;
                __nv_bfloat16 h;
                h = __float2bfloat16(v00); g_vth[iA]     = h;
                g_vtl[iA]     = __float2bfloat16(v00 - __bfloat162float(h));
                h = __float2bfloat16(v01); g_vth[iB]     = h;
                g_vtl[iB]     = __float2bfloat16(v01 - __bfloat162float(h));
                h = __float2bfloat16(v10); g_vth[iA + 8] = h;
                g_vtl[iA + 8] = __float2bfloat16(v10 - __bfloat162float(h));
                h = __float2bfloat16(v11); g_vth[iB + 8] = h;
                g_vtl[iB + 8] = __float2bfloat16(v11 - __bfloat162float(h));
            }
        }
    }
}

// ---------------------------------------------------------------------------
// Tensor-core flash attention. CTA = 64 queries, 256 threads (8 warps):
// mw = warp&3 -> 16-row group, nw = warp>>2 -> 32-key half. Each (mw,nw)
// warp runs an INDEPENDENT online softmax over its key half; the two halves
// merge once at the end (split-softmax identity). K/V staged via 2-stage
// cp.async pipeline; all inputs already split-bf16 (no conversion here).
// Smem: Q(2 tiles) + 2 x KV(4 tiles), tile = 64 rows x 72 bf16 (pad ->
// conflict-free fragment LDS). Total 92160 B, 2 CTAs/SM.
// ---------------------------------------------------------------------------
#define TILE  4608                      // bf16 elems per tile (64*72)
#define ATTN_SMEM_BYTES (10 * TILE * 2) // 92160

__global__ __launch_bounds__(256, 2) void attn_mma_kernel(float* __restrict__ out)
{
    extern __shared__ __nv_bfloat16 sm[];
    __nv_bfloat16* Qh = sm;
    __nv_bfloat16* Ql = sm + TILE;
    __nv_bfloat16* KV = sm + 2 * TILE;  // [2 bufs][Kh,Kl,Vth,Vtl]

    const int tid  = threadIdx.x;
    const int warp = tid >> 5;
    const int lane = tid & 31;
    const int g    = lane >> 2;
    const int tg   = lane & 3;
    const int mw   = warp & 3;          // 16-row group
    const int nw   = warp >> 2;         // key half
    const int qb   = blockIdx.x;        // 64-row query tile
    const int b    = blockIdx.y;
    const size_t base = (size_t)b * SEQ * NHEAD;
    const int q0   = qb * 64;

    const uint32_t smQh = smem_u32p(Qh);
    const uint32_t smKV = smem_u32p(KV);

    // staging geometry: tile = 64 rows x 8 16B-chunks; 2 chunks per thread
    const int sr0 = tid >> 3;            // row for chunk 0 (0..31)
    const int sc  = (tid & 7) * 16;      // byte offset within row

    const size_t rq = (size_t)b * SEQ + q0;     // global row of Q tile
    // prologue: stage Q + KV block 0
    {
        const char* qhs = (const char*)g_qh + rq * 128;
        const char* qls = (const char*)g_ql + rq * 128;
        cp16(smQh + sr0 * 144 + sc,                   qhs + sr0 * 128 + sc);
        cp16(smQh + (sr0 + 32) * 144 + sc,            qhs + (sr0 + 32) * 128 + sc);
        cp16(smQh + TILE * 2 + sr0 * 144 + sc,        qls + sr0 * 128 + sc);
        cp16(smQh + TILE * 2 + (sr0 + 32) * 144 + sc, qls + (sr0 + 32) * 128 + sc);
    }
    #define STAGE_KV(kb, buf) do {                                             \
        size_t rk_ = (size_t)b * SEQ + (size_t)(kb) * 64;                      \
        size_t rv_ = ((size_t)(b * 32 + (kb))) * 64;                           \
        uint32_t d0_ = smKV + (buf) * 4 * TILE * 2;                            \
        const char* s0_ = (const char*)g_kh  + rk_ * 128;                      \
        const char* s1_ = (const char*)g_kl  + rk_ * 128;                      \
        const char* s2_ = (const char*)g_vth + rv_ * 128;                      \
        const char* s3_ = (const char*)g_vtl + rv_ * 128;                      \
        _Pragma("unroll")                                                      \
        for (int i_ = 0; i_ < 2; i_++) {                                       \
            int r_ = sr0 + i_ * 32;                                            \
            uint32_t dd_ = d0_ + r_ * 144 + sc;                                \
            const size_t so_ = (size_t)r_ * 128 + sc;                          \
            cp16(dd_,                 s0_ + so_);                              \
            cp16(dd_ + 2 * TILE,      s1_ + so_);                              \
            cp16(dd_ + 4 * TILE,      s2_ + so_);                              \
            cp16(dd_ + 6 * TILE,      s3_ + so_);                              \
        }                                                                      \
    } while (0)

    STAGE_KV(0, 0);
    CP_COMMIT();

    float o[8][4];
    #pragma unroll
    for (int nb = 0; nb < 8; nb++)
        #pragma unroll
        for (int i = 0; i < 4; i++) o[nb][i] = 0.0f;
    float mrun[2] = {-1e30f, -1e30f};
    float lrun[2] = {0.0f, 0.0f};

    const uint32_t* Qh32 = (const uint32_t*)Qh;
    const uint32_t* Ql32 = (const uint32_t*)Ql;

    for (int kb = 0; kb <= qb; kb++) {
        if (kb > 0) __syncthreads();          // prior compute done -> alt buf free
        if (kb < qb) {
            STAGE_KV(kb + 1, (kb + 1) & 1);
            CP_COMMIT();
            CP_WAIT(1);
        } else {
            CP_WAIT(0);
        }
        __syncthreads();                      // staged data visible to all warps

        const uint32_t* Kh32  = (const uint32_t*)(KV + (kb & 1) * 4 * TILE);
        const uint32_t* Kl32  = Kh32 + TILE / 2;
        const uint32_t* Vth32 = Kh32 + TILE;
        const uint32_t* Vtl32 = Kh32 + 3 * TILE / 2;

        // ---- S = Q K^T over this warp's 32-key half (3-term split) ----
        float s[4][4];
        #pragma unroll
        for (int nb = 0; nb < 4; nb++)
            #pragma unroll
            for (int i = 0; i < 4; i++) s[nb][i] = 0.0f;

        #pragma unroll
        for (int ks = 0; ks < 4; ks++) {
            uint32_t qh[4], ql[4];
            uint32_t o0 = (mw * 16 + g) * 36 + ks * 8 + tg;
            uint32_t o1 = o0 + 8 * 36;
            qh[0] = Qh32[o0]; qh[1] = Qh32[o1];
            qh[2] = Qh32[o0 + 4]; qh[3] = Qh32[o1 + 4];
            ql[0] = Ql32[o0]; ql[1] = Ql32[o1];
            ql[2] = Ql32[o0 + 4]; ql[3] = Ql32[o1 + 4];
            #pragma unroll
            for (int nb = 0; nb < 4; nb++) {
                uint32_t ob = (nw * 32 + nb * 8 + g) * 36 + ks * 8 + tg;
                uint32_t bh[2], bl[2];
                bh[0] = Kh32[ob]; bh[1] = Kh32[ob + 4];
                bl[0] = Kl32[ob]; bl[1] = Kl32[ob + 4];
                mma_bf16(s[nb], qh, bh);
                mma_bf16(s[nb], qh, bl);
                mma_bf16(s[nb], ql, bh);
            }
        }

        // ---- causal mask (diagonal block only) ----
        if (kb == qb) {
            int r0 = q0 + mw * 16 + g;
            #pragma unroll
            for (int nb = 0; nb < 4; nb++) {
                int col = kb * 64 + nw * 32 + nb * 8 + 2 * tg;
                if (col     > r0)     s[nb][0] = -1e30f;
                if (col + 1 > r0)     s[nb][1] = -1e30f;
                if (col     > r0 + 8) s[nb][2] = -1e30f;
                if (col + 1 > r0 + 8) s[nb][3] = -1e30f;
            }
        }

        // ---- online softmax (base-2; quad reductions; per-warp half) ----
        float mx0 = -1e30f, mx1 = -1e30f;
        #pragma unroll
        for (int nb = 0; nb < 4; nb++) {
            mx0 = fmaxf(mx0, fmaxf(s[nb][0], s[nb][1]));
            mx1 = fmaxf(mx1, fmaxf(s[nb][2], s[nb][3]));
        }
        mx0 = fmaxf(mx0, __shfl_xor_sync(0xffffffffu, mx0, 1));
        mx0 = fmaxf(mx0, __shfl_xor_sync(0xffffffffu, mx0, 2));
        mx1 = fmaxf(mx1, __shfl_xor_sync(0xffffffffu, mx1, 1));
        mx1 = fmaxf(mx1, __shfl_xor_sync(0xffffffffu, mx1, 2));

        float mn0 = fmaxf(mrun[0], mx0);
        float mn1 = fmaxf(mrun[1], mx1);
        float corr0 = ex2(mrun[0] - mn0);
        float corr1 = ex2(mrun[1] - mn1);
        mrun[0] = mn0; mrun[1] = mn1;

        float ps0 = 0.0f, ps1 = 0.0f;
        #pragma unroll
        for (int nb = 0; nb < 4; nb++) {
            s[nb][0] = ex2(s[nb][0] - mn0);
            s[nb][1] = ex2(s[nb][1] - mn0);
            s[nb][2] = ex2(s[nb][2] - mn1);
            s[nb][3] = ex2(s[nb][3] - mn1);
            ps0 += s[nb][0] + s[nb][1];
            ps1 += s[nb][2] + s[nb][3];
        }
        ps0 += __shfl_xor_sync(0xffffffffu, ps0, 1);
        ps0 += __shfl_xor_sync(0xffffffffu, ps0, 2);
        ps1 += __shfl_xor_sync(0xffffffffu, ps1, 1);
        ps1 += __shfl_xor_sync(0xffffffffu, ps1, 2);
        lrun[0] = lrun[0] * corr0 + ps0;
        lrun[1] = lrun[1] * corr1 + ps1;

        #pragma unroll
        for (int nb = 0; nb < 8; nb++) {
            o[nb][0] *= corr0; o[nb][1] *= corr0;
            o[nb][2] *= corr1; o[nb][3] *= corr1;
        }

        // ---- O += P V (P from S fragments; V transposed in smem) ----
        #pragma unroll
        for (int ks = 0; ks < 2; ks++) {
            uint32_t ph[4], pl[4];
            ph[0] = pack_hi(s[2*ks][0],   s[2*ks][1]);
            ph[1] = pack_hi(s[2*ks][2],   s[2*ks][3]);
            ph[2] = pack_hi(s[2*ks+1][0], s[2*ks+1][1]);
            ph[3] = pack_hi(s[2*ks+1][2], s[2*ks+1][3]);
            pl[0] = pack_lo(s[2*ks][0],   s[2*ks][1]);
            pl[1] = pack_lo(s[2*ks][2],   s[2*ks][3]);
            pl[2] = pack_lo(s[2*ks+1][0], s[2*ks+1][1]);
            pl[3] = pack_lo(s[2*ks+1][2], s[2*ks+1][3]);
            #pragma unroll
            for (int nb = 0; nb < 8; nb++) {
                uint32_t ob = (nb * 8 + g) * 36 + nw * 16 + ks * 8 + tg;
                uint32_t vh[2], vl[2];
                vh[0] = Vth32[ob]; vh[1] = Vth32[ob + 4];
                vl[0] = Vtl32[ob]; vl[1] = Vtl32[ob + 4];
                mma_bf16(o[nb], ph, vh);
                mma_bf16(o[nb], ph, vl);
                mma_bf16(o[nb], pl, vh);
            }
        }
    }

    // ---- split-softmax merge across the two key halves + store ----
    __syncthreads();                      // compute done; smem reusable
    float* Of = (float*)KV;               // 64 x 66 f32 (even stride: float2 ok)
    float* Ml = (float*)sm;               // m[64], l[64] (Q area, done)
    const int r0l = mw * 16 + g;

    if (nw == 1) {
        if (tg == 0) {
            Ml[r0l]          = mrun[0];
            Ml[64 + r0l]     = lrun[0];
            Ml[r0l + 8]      = mrun[1];
            Ml[64 + r0l + 8] = lrun[1];
        }
        #pragma unroll
        for (int nb = 0; nb < 8; nb++) {
            int col = nb * 8 + 2 * tg;
            *(float2*)&Of[r0l * 66 + col]       = make_float2(o[nb][0], o[nb][1]);
            *(float2*)&Of[(r0l + 8) * 66 + col] = make_float2(o[nb][2], o[nb][3]);
        }
    }
    __syncthreads();
    if (nw == 0) {
        float m1a = Ml[r0l],     l1a = Ml[64 + r0l];
        float m1b = Ml[r0l + 8], l1b = Ml[64 + r0l + 8];
        float ma = fmaxf(mrun[0], m1a), mb = fmaxf(mrun[1], m1b);
        float c0a = ex2(mrun[0] - ma), c1a = ex2(m1a - ma);
        float c0b = ex2(mrun[1] - mb), c1b = ex2(m1b - mb);
        float ia = 1.0f / (c0a * lrun[0] + c1a * l1a);
        float ib = 1.0f / (c0b * lrun[1] + c1b * l1b);
        float* oa = out + base + (size_t)(q0 + r0l) * NHEAD;
        float* ob = out + base + (size_t)(q0 + r0l + 8) * NHEAD;
        #pragma unroll
        for (int nb = 0; nb < 8; nb++) {
            int col = nb * 8 + 2 * tg;
            float2 p1 = *(float2*)&Of[r0l * 66 + col];
            float2 p2 = *(float2*)&Of[(r0l + 8) * 66 + col];
            *(float2*)(oa + col) = make_float2((c0a * o[nb][0] + c1a * p1.x) * ia,
                                               (c0a * o[nb][1] + c1a * p1.y) * ia);
            *(float2*)(ob + col) = make_float2((c0b * o[nb][2] + c1b * p2.x) * ib,
                                               (c0b * o[nb][3] + c1b * p2.y) * ib);
        }
    }
}

// ---------------------------------------------------------------------------
extern "C" void kernel_launch(void* const* d_in, const int* in_sizes, int n_in,
                              void* d_out, int out_size)
{
    (void)in_sizes; (void)n_in; (void)out_size;
    const float* x  = (const float*)d_in[0];
    const float* Wk = (const float*)d_in[1];
    const float* Wq = (const float*)d_in[2];
    const float* Wv = (const float*)d_in[3];
    float* out = (float*)d_out;

    cudaFuncSetAttribute(attn_mma_kernel,
                         cudaFuncAttributeMaxDynamicSharedMemorySize,
                         ATTN_SMEM_BYTES);

    qkv_mma_kernel<<<dim3(ROWS / 64, 1, 1), 256>>>(x, Wk, Wq, Wv);
    attn_mma_kernel<<<dim3(SEQ / 64, BATCH, 1), 256, ATTN_SMEM_BYTES>>>(out);
}

// round 10
// speedup vs baseline: 2.6830x; 1.2592x over previous
#include <cuda_runtime.h>
#include <cuda_bf16.h>
#include <cstdint>

#define SEQ   2048
#define EMB   1024
#define NHEAD 64
#define BATCH 8
#define ROWS  (BATCH*SEQ)   // 16384

// Split-bf16 scratch (allocation-free device globals, 16B-aligned for cp.async).
// q/k: [row][64] as u32 pairs. v: transposed per 64-row block.
__device__ __align__(16) uint32_t      g_qh[(size_t)ROWS * 32], g_ql[(size_t)ROWS * 32];
__device__ __align__(16) uint32_t      g_kh[(size_t)ROWS * 32], g_kl[(size_t)ROWS * 32];
__device__ __align__(16) __nv_bfloat16 g_vth[(size_t)ROWS * 64], g_vtl[(size_t)ROWS * 64];
// Pre-split weights, chunk-tiled: [chunk c][row r][kk], r<192 = hi(n=r),
// r>=192 = lo(n=r-192). n: 0-63 Q (QSCALE folded), 64-127 K, 128-191 V.
__device__ __align__(16) __nv_bfloat16 g_wsp[(size_t)32 * 384 * 32];

#define QSCALE 0.1803368801111243f   // 0.125 * log2(e): base-2 softmax

// ---------------------------------------------------------------------------
// Helpers
// ---------------------------------------------------------------------------
__device__ __forceinline__ void split2(float vx, float vy,
                                       uint32_t& hi, uint32_t& lo)
{
    __nv_bfloat16 hx = __float2bfloat16(vx);
    __nv_bfloat16 hy = __float2bfloat16(vy);
    __nv_bfloat16 lx = __float2bfloat16(vx - __bfloat162float(hx));
    __nv_bfloat16 ly = __float2bfloat16(vy - __bfloat162float(hy));
    hi = ((uint32_t)__bfloat16_as_ushort(hy) << 16) | __bfloat16_as_ushort(hx);
    lo = ((uint32_t)__bfloat16_as_ushort(ly) << 16) | __bfloat16_as_ushort(lx);
}

__device__ __forceinline__ void mma_bf16(float* c, const uint32_t* a,
                                         const uint32_t* b)
{
    asm volatile(
        "mma.sync.aligned.m16n8k16.row.col.f32.bf16.bf16.f32 "
        "{%0,%1,%2,%3}, {%4,%5,%6,%7}, {%8,%9}, {%0,%1,%2,%3};"
        : "+f"(c[0]), "+f"(c[1]), "+f"(c[2]), "+f"(c[3])
        : "r"(a[0]), "r"(a[1]), "r"(a[2]), "r"(a[3]), "r"(b[0]), "r"(b[1]));
}

__device__ __forceinline__ float ex2(float x) {
    float y;
    asm("ex2.approx.f32 %0, %1;" : "=f"(y) : "f"(x));
    return y;
}

__device__ __forceinline__ uint32_t pack_hi(float a, float b) {
    return ((uint32_t)__bfloat16_as_ushort(__float2bfloat16(b)) << 16) |
           __bfloat16_as_ushort(__float2bfloat16(a));
}
__device__ __forceinline__ uint32_t pack_lo(float a, float b) {
    float ra = a - __bfloat162float(__float2bfloat16(a));
    float rb = b - __bfloat162float(__float2bfloat16(b));
    return pack_hi(ra, rb);
}

__device__ __forceinline__ uint32_t smem_u32p(const void* p) {
    uint32_t a;
    asm("{ .reg .u64 t; cvta.to.shared.u64 t, %1; cvt.u32.u64 %0, t; }"
        : "=r"(a) : "l"(p));
    return a;
}
__device__ __forceinline__ void cp16(uint32_t dst, const void* src) {
    asm volatile("cp.async.ca.shared.global [%0], [%1], 16;"
                 :: "r"(dst), "l"(src));
}
#define CP_COMMIT()  asm volatile("cp.async.commit_group;" ::: "memory")
#define CP_WAIT(n)   asm volatile("cp.async.wait_group %0;" :: "n"(n) : "memory")

// ---------------------------------------------------------------------------
// Prologue: split W (f32) -> chunk-tiled split-bf16, QSCALE folded into Wq.
// ---------------------------------------------------------------------------
__global__ __launch_bounds__(256) void wsplit_kernel(
    const float* __restrict__ Wk,
    const float* __restrict__ Wq,
    const float* __restrict__ Wv)
{
    int idx = blockIdx.x * 256 + threadIdx.x;   // 0..196607 = (c*32+kk)*192 + n
    int n  = idx % 192;
    int t  = idx / 192;
    int kk = t & 31;
    int c  = t >> 5;
    int k  = c * 32 + kk;
    const float* Wp = (n < 64) ? Wq : ((n < 128) ? Wk : Wv);
    float v = Wp[(size_t)k * NHEAD + (n & 63)];
    if (n < 64) v *= QSCALE;
    __nv_bfloat16 h = __float2bfloat16(v);
    __nv_bfloat16 l = __float2bfloat16(v - __bfloat162float(h));
    g_wsp[((size_t)c * 384 + n) * 32 + kk]       = h;
    g_wsp[((size_t)c * 384 + 192 + n) * 32 + kk] = l;
}

// ---------------------------------------------------------------------------
// QKV projection via mma.sync bf16 (2-term split). M=64/CTA (grid 256),
// N=192 fused, K in 32-wide chunks. x register-prefetched + split in-kernel;
// W pre-split, staged via cp.async double buffer (no per-chunk conversion).
// B smem: rows padded to 40 bf16 (80B) -> 16B-aligned cp.async dsts and
// conflict-free fragment banks (20g+tg mod 32 distinct).
// ---------------------------------------------------------------------------
__global__ __launch_bounds__(256, 2) void qkv_mma_kernel(
    const float* __restrict__ x,
    const float* __restrict__ Wk,
    const float* __restrict__ Wq,
    const float* __restrict__ Wv)
{
    __shared__ __nv_bfloat16 Ah[64 * 36], Al[64 * 36];
    __shared__ __nv_bfloat16 Bsm[2 * 384 * 40];   // 61440 B

    const int tid  = threadIdx.x;
    const int warp = tid >> 5;
    const int lane = tid & 31;
    const int g    = lane >> 2;
    const int tg   = lane & 3;
    const int mg   = warp & 1;        // 32-row half
    const int ng   = warp >> 1;       // 48-col group
    const int m0   = blockIdx.x * 64;

    const uint32_t smB = smem_u32p(Bsm);

    float acc[2][6][4];
    #pragma unroll
    for (int mt = 0; mt < 2; mt++)
        #pragma unroll
        for (int nb = 0; nb < 6; nb++)
            #pragma unroll
            for (int i = 0; i < 4; i++) acc[mt][nb][i] = 0.0f;

    // x register prefetch geometry
    float4 xa[2];
    const int xr  = tid >> 3;
    const int xc4 = (tid & 7) * 4;

    #define LOAD_X(chunk) do {                                                 \
        int k0_ = (chunk) * 32;                                                \
        xa[0] = *(const float4*)(x + (size_t)(m0 + xr) * EMB + k0_ + xc4);     \
        xa[1] = *(const float4*)(x + (size_t)(m0 + xr + 32) * EMB + k0_ + xc4);\
    } while (0)

    // B staging: 384 rows x 64B = 1536 16B-chunks, 6 per thread
    const int br = tid >> 2;          // row 0..63 (plus +64*j)
    const int bp = (tid & 3) * 16;    // 16B part
    #define STAGE_B(chunk, buf) do {                                           \
        const char* src_ = (const char*)g_wsp + (size_t)(chunk) * 384 * 64;    \
        uint32_t d_ = smB + (buf) * 30720;                                     \
        _Pragma("unroll")                                                      \
        for (int j_ = 0; j_ < 6; j_++) {                                       \
            int r_ = br + j_ * 64;                                             \
            cp16(d_ + r_ * 80 + bp, src_ + (size_t)r_ * 64 + bp);              \
        }                                                                      \
    } while (0)

    STAGE_B(0, 0);
    CP_COMMIT();
    LOAD_X(0);

    for (int chunk = 0; chunk < 32; chunk++) {
        __syncthreads();   // prev mma reads of Ah/Al and Bsm[alt] done

        // ---- store staged x regs -> smem (with split) ----
        #pragma unroll
        for (int i = 0; i < 2; i++) {
            int r = xr + i * 32;
            uint32_t h0, l0, h1, l1;
            split2(xa[i].x, xa[i].y, h0, l0);
            split2(xa[i].z, xa[i].w, h1, l1);
            uint32_t off = r * 36 + xc4;
            *(uint32_t*)(Ah + off)     = h0;
            *(uint32_t*)(Ah + off + 2) = h1;
            *(uint32_t*)(Al + off)     = l0;
            *(uint32_t*)(Al + off + 2) = l1;
        }
        if (chunk < 31) {
            STAGE_B(chunk + 1, (chunk + 1) & 1);
            CP_COMMIT();
            CP_WAIT(1);    // B(chunk) arrived
        } else {
            CP_WAIT(0);
        }
        __syncthreads();   // A stores + B(chunk) visible to all

        if (chunk < 31) LOAD_X(chunk + 1);   // overlap with MMAs below

        const __nv_bfloat16* Bb = Bsm + (chunk & 1) * 15360;

        #pragma unroll
        for (int ks = 0; ks < 2; ks++) {
            uint32_t ah[2][4], al2[2][4];
            #pragma unroll
            for (int mt = 0; mt < 2; mt++) {
                int r0 = mg * 32 + mt * 16 + g;
                uint32_t o0 = r0 * 36 + ks * 16 + 2 * tg;   // bf16 index
                uint32_t o1 = o0 + 8 * 36;
                ah[mt][0] = *(const uint32_t*)(Ah + o0);
                ah[mt][1] = *(const uint32_t*)(Ah + o1);
                ah[mt][2] = *(const uint32_t*)(Ah + o0 + 8);
                ah[mt][3] = *(const uint32_t*)(Ah + o1 + 8);
                al2[mt][0] = *(const uint32_t*)(Al + o0);
                al2[mt][1] = *(const uint32_t*)(Al + o1);
                al2[mt][2] = *(const uint32_t*)(Al + o0 + 8);
                al2[mt][3] = *(const uint32_t*)(Al + o1 + 8);
            }
            #pragma unroll
            for (int nb = 0; nb < 6; nb++) {
                int n = ng * 48 + nb * 8 + g;
                uint32_t obh = n * 40 + ks * 16 + 2 * tg;          // hi row
                uint32_t obl = obh + 192 * 40;                      // lo row
                uint32_t bh[2], bl[2];
                bh[0] = *(const uint32_t*)(Bb + obh);
                bh[1] = *(const uint32_t*)(Bb + obh + 8);
                bl[0] = *(const uint32_t*)(Bb + obl);
                bl[1] = *(const uint32_t*)(Bb + obl + 8);
                #pragma unroll
                for (int mt = 0; mt < 2; mt++) {
                    mma_bf16(acc[mt][nb], ah[mt], bh);
                    mma_bf16(acc[mt][nb], ah[mt], bl);
                    mma_bf16(acc[mt][nb], al2[mt], bh);
                }
            }
        }
    }

    // ---- epilogue: write split-bf16 q/k (row-major) and v (transposed) ----
    const int b_  = m0 >> 11;          // batch
    const int kb_ = (m0 >> 6) & 31;    // 64-block within seq
    const size_t vrow0 = ((size_t)(b_ * 32 + kb_)) * 64;

    #pragma unroll
    for (int mt = 0; mt < 2; mt++) {
        size_t r0 = (size_t)m0 + mg * 32 + mt * 16 + g;
        int    t0 = (int)(r0 & 63);
        #pragma unroll
        for (int nb = 0; nb < 6; nb++) {
            int n0  = ng * 48 + nb * 8;
            int w   = n0 >> 6;
            int col = (n0 & 63) + 2 * tg;
            float v00 = acc[mt][nb][0], v01 = acc[mt][nb][1];
            float v10 = acc[mt][nb][2], v11 = acc[mt][nb][3];
            if (w == 0) {                       // QSCALE already folded into Wq
                size_t i0 = r0 * 32 + (col >> 1);
                g_qh[i0]       = pack_hi(v00, v01);
                g_ql[i0]       = pack_lo(v00, v01);
                g_qh[i0 + 256] = pack_hi(v10, v11);
                g_ql[i0 + 256] = pack_lo(v10, v11);
            } else if (w == 1) {
                size_t i0 = r0 * 32 + (col >> 1);
                g_kh[i0]       = pack_hi(v00, v01);
                g_kl[i0]       = pack_lo(v00, v01);
                g_kh[i0 + 256] = pack_hi(v10, v11);
                g_kl[i0 + 256] = pack_lo(v10, v11);
            } else {
                size_t iA = (vrow0 + col) * 64 + t0;
                size_t iB = (vrow0 + col + 1) * 64 + t0;
                __nv_bfloat16 h;
                h = __float2bfloat16(v00); g_vth[iA]     = h;
                g_vtl[iA]     = __float2bfloat16(v00 - __bfloat162float(h));
                h = __float2bfloat16(v01); g_vth[iB]     = h;
                g_vtl[iB]     = __float2bfloat16(v01 - __bfloat162float(h));
                h = __float2bfloat16(v10); g_vth[iA + 8] = h;
                g_vtl[iA + 8] = __float2bfloat16(v10 - __bfloat162float(h));
                h = __float2bfloat16(v11); g_vth[iB + 8] = h;
                g_vtl[iB + 8] = __float2bfloat16(v11 - __bfloat162float(h));
            }
        }
    }
}

// ---------------------------------------------------------------------------
// Tensor-core flash attention (unchanged from R8's passing version).
// CTA = 64 queries, 8 warps: mw = 16-row group, nw = 32-key half, split
// softmax merged once at the end. 2-stage cp.async K/V pipeline.
// ---------------------------------------------------------------------------
#define TILE  4608                      // bf16 elems per tile (64*72)
#define ATTN_SMEM_BYTES (10 * TILE * 2) // 92160

__global__ __launch_bounds__(256, 2) void attn_mma_kernel(float* __restrict__ out)
{
    extern __shared__ __nv_bfloat16 sm[];
    __nv_bfloat16* Qh = sm;
    __nv_bfloat16* Ql = sm + TILE;
    __nv_bfloat16* KV = sm + 2 * TILE;  // [2 bufs][Kh,Kl,Vth,Vtl]

    const int tid  = threadIdx.x;
    const int warp = tid >> 5;
    const int lane = tid & 31;
    const int g    = lane >> 2;
    const int tg   = lane & 3;
    const int mw   = warp & 3;
    const int nw   = warp >> 2;
    const int qb   = blockIdx.x;
    const int b    = blockIdx.y;
    const size_t base = (size_t)b * SEQ * NHEAD;
    const int q0   = qb * 64;

    const uint32_t smQh = smem_u32p(Qh);
    const uint32_t smKV = smem_u32p(KV);

    const int sr0 = tid >> 3;
    const int sc  = (tid & 7) * 16;

    const size_t rq = (size_t)b * SEQ + q0;
    {
        const char* qhs = (const char*)g_qh + rq * 128;
        const char* qls = (const char*)g_ql + rq * 128;
        cp16(smQh + sr0 * 144 + sc,                   qhs + sr0 * 128 + sc);
        cp16(smQh + (sr0 + 32) * 144 + sc,            qhs + (sr0 + 32) * 128 + sc);
        cp16(smQh + TILE * 2 + sr0 * 144 + sc,        qls + sr0 * 128 + sc);
        cp16(smQh + TILE * 2 + (sr0 + 32) * 144 + sc, qls + (sr0 + 32) * 128 + sc);
    }
    #define STAGE_KV(kb, buf) do {                                             \
        size_t rk_ = (size_t)b * SEQ + (size_t)(kb) * 64;                      \
        size_t rv_ = ((size_t)(b * 32 + (kb))) * 64;                           \
        uint32_t d0_ = smKV + (buf) * 4 * TILE * 2;                            \
        const char* s0_ = (const char*)g_kh  + rk_ * 128;                      \
        const char* s1_ = (const char*)g_kl  + rk_ * 128;                      \
        const char* s2_ = (const char*)g_vth + rv_ * 128;                      \
        const char* s3_ = (const char*)g_vtl + rv_ * 128;                      \
        _Pragma("unroll")                                                      \
        for (int i_ = 0; i_ < 2; i_++) {                                       \
            int r_ = sr0 + i_ * 32;                                            \
            uint32_t dd_ = d0_ + r_ * 144 + sc;                                \
            const size_t so_ = (size_t)r_ * 128 + sc;                          \
            cp16(dd_,                 s0_ + so_);                              \
            cp16(dd_ + 2 * TILE,      s1_ + so_);                              \
            cp16(dd_ + 4 * TILE,      s2_ + so_);                              \
            cp16(dd_ + 6 * TILE,      s3_ + so_);                              \
        }                                                                      \
    } while (0)

    STAGE_KV(0, 0);
    CP_COMMIT();

    float o[8][4];
    #pragma unroll
    for (int nb = 0; nb < 8; nb++)
        #pragma unroll
        for (int i = 0; i < 4; i++) o[nb][i] = 0.0f;
    float mrun[2] = {-1e30f, -1e30f};
    float lrun[2] = {0.0f, 0.0f};

    const uint32_t* Qh32 = (const uint32_t*)Qh;
    const uint32_t* Ql32 = (const uint32_t*)Ql;

    for (int kb = 0; kb <= qb; kb++) {
        if (kb > 0) __syncthreads();
        if (kb < qb) {
            STAGE_KV(kb + 1, (kb + 1) & 1);
            CP_COMMIT();
            CP_WAIT(1);
        } else {
            CP_WAIT(0);
        }
        __syncthreads();

        const uint32_t* Kh32  = (const uint32_t*)(KV + (kb & 1) * 4 * TILE);
        const uint32_t* Kl32  = Kh32 + TILE / 2;
        const uint32_t* Vth32 = Kh32 + TILE;
        const uint32_t* Vtl32 = Kh32 + 3 * TILE / 2;

        float s[4][4];
        #pragma unroll
        for (int nb = 0; nb < 4; nb++)
            #pragma unroll
            for (int i = 0; i < 4; i++) s[nb][i] = 0.0f;

        #pragma unroll
        for (int ks = 0; ks < 4; ks++) {
            uint32_t qh[4], ql[4];
            uint32_t o0 = (mw * 16 + g) * 36 + ks * 8 + tg;
            uint32_t o1 = o0 + 8 * 36;
            qh[0] = Qh32[o0]; qh[1] = Qh32[o1];
            qh[2] = Qh32[o0 + 4]; qh[3] = Qh32[o1 + 4];
            ql[0] = Ql32[o0]; ql[1] = Ql32[o1];
            ql[2] = Ql32[o0 + 4]; ql[3] = Ql32[o1 + 4];
            #pragma unroll
            for (int nb = 0; nb < 4; nb++) {
                uint32_t ob = (nw * 32 + nb * 8 + g) * 36 + ks * 8 + tg;
                uint32_t bh[2], bl[2];
                bh[0] = Kh32[ob]; bh[1] = Kh32[ob + 4];
                bl[0] = Kl32[ob]; bl[1] = Kl32[ob + 4];
                mma_bf16(s[nb], qh, bh);
                mma_bf16(s[nb], qh, bl);
                mma_bf16(s[nb], ql, bh);
            }
        }

        if (kb == qb) {
            int r0 = q0 + mw * 16 + g;
            #pragma unroll
            for (int nb = 0; nb < 4; nb++) {
                int col = kb * 64 + nw * 32 + nb * 8 + 2 * tg;
                if (col     > r0)     s[nb][0] = -1e30f;
                if (col + 1 > r0)     s[nb][1] = -1e30f;
                if (col     > r0 + 8) s[nb][2] = -1e30f;
                if (col + 1 > r0 + 8) s[nb][3] = -1e30f;
            }
        }

        float mx0 = -1e30f, mx1 = -1e30f;
        #pragma unroll
        for (int nb = 0; nb < 4; nb++) {
            mx0 = fmaxf(mx0, fmaxf(s[nb][0], s[nb][1]));
            mx1 = fmaxf(mx1, fmaxf(s[nb][2], s[nb][3]));
        }
        mx0 = fmaxf(mx0, __shfl_xor_sync(0xffffffffu, mx0, 1));
        mx0 = fmaxf(mx0, __shfl_xor_sync(0xffffffffu, mx0, 2));
        mx1 = fmaxf(mx1, __shfl_xor_sync(0xffffffffu, mx1, 1));
        mx1 = fmaxf(mx1, __shfl_xor_sync(0xffffffffu, mx1, 2));

        float mn0 = fmaxf(mrun[0], mx0);
        float mn1 = fmaxf(mrun[1], mx1);
        float corr0 = ex2(mrun[0] - mn0);
        float corr1 = ex2(mrun[1] - mn1);
        mrun[0] = mn0; mrun[1] = mn1;

        float ps0 = 0.0f, ps1 = 0.0f;
        #pragma unroll
        for (int nb = 0; nb < 4; nb++) {
            s[nb][0] = ex2(s[nb][0] - mn0);
            s[nb][1] = ex2(s[nb][1] - mn0);
            s[nb][2] = ex2(s[nb][2] - mn1);
            s[nb][3] = ex2(s[nb][3] - mn1);
            ps0 += s[nb][0] + s[nb][1];
            ps1 += s[nb][2] + s[nb][3];
        }
        ps0 += __shfl_xor_sync(0xffffffffu, ps0, 1);
        ps0 += __shfl_xor_sync(0xffffffffu, ps0, 2);
        ps1 += __shfl_xor_sync(0xffffffffu, ps1, 1);
        ps1 += __shfl_xor_sync(0xffffffffu, ps1, 2);
        lrun[0] = lrun[0] * corr0 + ps0;
        lrun[1] = lrun[1] * corr1 + ps1;

        #pragma unroll
        for (int nb = 0; nb < 8; nb++) {
            o[nb][0] *= corr0; o[nb][1] *= corr0;
            o[nb][2] *= corr1; o[nb][3] *= corr1;
        }

        #pragma unroll
        for (int ks = 0; ks < 2; ks++) {
            uint32_t ph[4], pl[4];
            ph[0] = pack_hi(s[2*ks][0],   s[2*ks][1]);
            ph[1] = pack_hi(s[2*ks][2],   s[2*ks][3]);
            ph[2] = pack_hi(s[2*ks+1][0], s[2*ks+1][1]);
            ph[3] = pack_hi(s[2*ks+1][2], s[2*ks+1][3]);
            pl[0] = pack_lo(s[2*ks][0],   s[2*ks][1]);
            pl[1] = pack_lo(s[2*ks][2],   s[2*ks][3]);
            pl[2] = pack_lo(s[2*ks+1][0], s[2*ks+1][1]);
            pl[3] = pack_lo(s[2*ks+1][2], s[2*ks+1][3]);
            #pragma unroll
            for (int nb = 0; nb < 8; nb++) {
                uint32_t ob = (nb * 8 + g) * 36 + nw * 16 + ks * 8 + tg;
                uint32_t vh[2], vl[2];
                vh[0] = Vth32[ob]; vh[1] = Vth32[ob + 4];
                vl[0] = Vtl32[ob]; vl[1] = Vtl32[ob + 4];
                mma_bf16(o[nb], ph, vh);
                mma_bf16(o[nb], ph, vl);
                mma_bf16(o[nb], pl, vh);
            }
        }
    }

    __syncthreads();
    float* Of = (float*)KV;               // 64 x 66 f32 (even stride)
    float* Ml = (float*)sm;
    const int r0l = mw * 16 + g;

    if (nw == 1) {
        if (tg == 0) {
            Ml[r0l]          = mrun[0];
            Ml[64 + r0l]     = lrun[0];
            Ml[r0l + 8]      = mrun[1];
            Ml[64 + r0l + 8] = lrun[1];
        }
        #pragma unroll
        for (int nb = 0; nb < 8; nb++) {
            int col = nb * 8 + 2 * tg;
            *(float2*)&Of[r0l * 66 + col]       = make_float2(o[nb][0], o[nb][1]);
            *(float2*)&Of[(r0l + 8) * 66 + col] = make_float2(o[nb][2], o[nb][3]);
        }
    }
    __syncthreads();
    if (nw == 0) {
        float m1a = Ml[r0l],     l1a = Ml[64 + r0l];
        float m1b = Ml[r0l + 8], l1b = Ml[64 + r0l + 8];
        float ma = fmaxf(mrun[0], m1a), mb = fmaxf(mrun[1], m1b);
        float c0a = ex2(mrun[0] - ma), c1a = ex2(m1a - ma);
        float c0b = ex2(mrun[1] - mb), c1b = ex2(m1b - mb);
        float ia = 1.0f / (c0a * lrun[0] + c1a * l1a);
        float ib = 1.0f / (c0b * lrun[1] + c1b * l1b);
        float* oa = out + base + (size_t)(q0 + r0l) * NHEAD;
        float* ob = out + base + (size_t)(q0 + r0l + 8) * NHEAD;
        #pragma unroll
        for (int nb = 0; nb < 8; nb++) {
            int col = nb * 8 + 2 * tg;
            float2 p1 = *(float2*)&Of[r0l * 66 + col];
            float2 p2 = *(float2*)&Of[(r0l + 8) * 66 + col];
            *(float2*)(oa + col) = make_float2((c0a * o[nb][0] + c1a * p1.x) * ia,
                                               (c0a * o[nb][1] + c1a * p1.y) * ia);
            *(float2*)(ob + col) = make_float2((c0b * o[nb][2] + c1b * p2.x) * ib,
                                               (c0b * o[nb][3] + c1b * p2.y) * ib);
        }
    }
}

// ---------------------------------------------------------------------------
extern "C" void kernel_launch(void* const* d_in, const int* in_sizes, int n_in,
                              void* d_out, int out_size)
{
    (void)in_sizes; (void)n_in; (void)out_size;
    const float* x  = (const float*)d_in[0];
    const float* Wk = (const float*)d_in[1];
    const float* Wq = (const float*)d_in[2];
    const float* Wv = (const float*)d_in[3];
    float* out = (float*)d_out;

    cudaFuncSetAttribute(attn_mma_kernel,
                         cudaFuncAttributeMaxDynamicSharedMemorySize,
                         ATTN_SMEM_BYTES);

    wsplit_kernel<<<dim3(768, 1, 1), 256>>>(Wk, Wq, Wv);
    qkv_mma_kernel<<<dim3(ROWS / 64, 1, 1), 256>>>(x, Wk, Wq, Wv);
    attn_mma_kernel<<<dim3(SEQ / 64, BATCH, 1), 256, ATTN_SMEM_BYTES>>>(out);
}